// round 14
// baseline (speedup 1.0000x reference)
#include <cuda_runtime.h>
#include <cuda_fp16.h>
#include <cstdint>
#include <math.h>

#define NN 20000
#define EE 200000
#define HD 256
#define NHEADS 4
#define NDIM 128
#define EDIM 64
#define NL 3

// merged K-major fp16 weight buffer layout
#define ENC_OFF 0
#define ENC_SZ (256 * 128)
#define GAT_OFF ENC_SZ
#define GAT_SZ (1024 * 256)
#define HEAD_OFF (ENC_SZ + 3 * GAT_SZ)
#define HEAD_SZ (512 * 256)
#define WTOT (HEAD_OFF + HEAD_SZ)

// ---------------- scratch (static device globals; no runtime allocation) ----------------
__device__ __half g_xph[(size_t)NN * NHEADS * HD];  // xp in fp16 [N,1024]
__device__ float g_as [NN * NHEADS];
__device__ float g_ad [NN * NHEADS];
__device__ float g_ew [NL * EE];
__device__ float g_loopw[NL * NN];
__device__ int   g_counts[NN];
__device__ int   g_cursor[NN];
__device__ int   g_rowptr[NN + 1];
__device__ int   g_csrc[EE];
__device__ int   g_ceid[EE];
__device__ float g_hmid[(size_t)NN * 512];
__device__ float g_wmean[NL * EDIM];
__device__ float g_bmean[NL];
__device__ float g_cvec [NL * NHEADS];
__device__ float g_vv  [NL * 8 * 256];      // v[l][u][d]: u = sd*4+h (sd 0=src,1=dst)
// fp16 hi/lo split buffers
__device__ __half g_Ah[(size_t)NN * HD];    // encoder input split
__device__ __half g_Al[(size_t)NN * HD];
__device__ __half g_Xh[(size_t)NN * HD];    // activation x split (exact fp32 = hi+lo)
__device__ __half g_Xl[(size_t)NN * HD];
__device__ __half g_Wh[WTOT];               // all weights K-major, hi
__device__ __half g_Wl[WTOT];               // lo

// ---------------- helpers ----------------
__device__ __forceinline__ float lrelu(float x) { return fmaxf(x, 0.2f * x); }

__device__ __forceinline__ void mma16816(float* c, const uint32_t* a, const uint32_t* b) {
    asm volatile(
        "mma.sync.aligned.m16n8k16.row.col.f32.f16.f16.f32 "
        "{%0,%1,%2,%3}, {%4,%5,%6,%7}, {%8,%9}, {%0,%1,%2,%3};"
        : "+f"(c[0]), "+f"(c[1]), "+f"(c[2]), "+f"(c[3])
        : "r"(a[0]), "r"(a[1]), "r"(a[2]), "r"(a[3]), "r"(b[0]), "r"(b[1]));
}
__device__ __forceinline__ void ldsm4(uint32_t addr, uint32_t* r) {
    asm volatile("ldmatrix.sync.aligned.m8n8.x4.shared.b16 {%0,%1,%2,%3}, [%4];"
                 : "=r"(r[0]), "=r"(r[1]), "=r"(r[2]), "=r"(r[3]) : "r"(addr));
}
__device__ __forceinline__ void cpa16z(uint32_t dst, const void* src, int sz) {
    asm volatile("cp.async.cg.shared.global [%0], [%1], 16, %2;"
                 :: "r"(dst), "l"(src), "r"(sz));
}
__device__ __forceinline__ float4 h4tof4(uint2 u) {
    __half2 a = *(__half2*)&u.x, b = *(__half2*)&u.y;
    float2 fa = __half22float2(a), fb = __half22float2(b);
    return make_float4(fa.x, fa.y, fb.x, fb.y);
}

// ---------------- fp16x3 GEMM (A,B both hi/lo split), double-buffered cp.async ----------------
#define KCH 32
#define AST 40
#define STG (128 * AST)
#define GEMM_SMEM (8 * STG * 2)      // 81920 bytes
__global__ __launch_bounds__(256, 2) void k_mma(
    const __half* __restrict__ Ah, const __half* __restrict__ Al,
    const __half* __restrict__ Bh, const __half* __restrict__ Bl,
    float* __restrict__ C, __half* __restrict__ Cxp,
    __half* __restrict__ Chi, __half* __restrict__ Clo,
    int M, int N, int K, const float* __restrict__ bias, int doRelu) {
    extern __shared__ __half sm[];
    uint32_t base = (uint32_t)__cvta_generic_to_shared(sm);

    int tid = threadIdx.x, lane = tid & 31, wid = tid >> 5;
    int nb = blockIdx.x, mb = blockIdx.y;
    int warpM = wid >> 2, warpN = wid & 3;
    int gid = lane >> 2, qid = lane & 3;
    int NC = K / KCH;

    auto offAh = [&](int s) { return base + (uint32_t)(4 * s) * STG * 2; };
    auto offAl = [&](int s) { return base + (uint32_t)(4 * s + 1) * STG * 2; };
    auto offBh = [&](int s) { return base + (uint32_t)(4 * s + 2) * STG * 2; };
    auto offBl = [&](int s) { return base + (uint32_t)(4 * s + 3) * STG * 2; };

    auto load_chunk = [&](int kc, int s) {
        int k0 = kc * KCH;
#pragma unroll
        for (int i = tid; i < 512; i += 256) {
            int row = i >> 2, c = i & 3;
            uint32_t so = (uint32_t)(row * AST + c * 8) * 2;
            int gr = mb * 128 + row;
            int sz = (gr < M) ? 16 : 0;
            int grc = (gr < M) ? gr : (M - 1);
            cpa16z(offAh(s) + so, Ah + (size_t)grc * K + k0 + c * 8, sz);
            cpa16z(offAl(s) + so, Al + (size_t)grc * K + k0 + c * 8, sz);
            int gn = nb * 128 + row;
            cpa16z(offBh(s) + so, Bh + (size_t)gn * K + k0 + c * 8, 16);
            cpa16z(offBl(s) + so, Bl + (size_t)gn * K + k0 + c * 8, 16);
        }
        asm volatile("cp.async.commit_group;");
    };

    float acc[4][4][4];
#pragma unroll
    for (int i = 0; i < 4; i++)
#pragma unroll
        for (int j = 0; j < 4; j++)
#pragma unroll
            for (int k = 0; k < 4; k++) acc[i][j][k] = 0.f;

    int aRow = (lane & 15), aCol = (lane >> 4) * 8;
    int bRow = (lane & 7) + ((lane >> 4) << 3), bCol = ((lane >> 3) & 1) * 8;

    load_chunk(0, 0);

    for (int kc = 0; kc < NC; kc++) {
        int s = kc & 1;
        if (kc + 1 < NC) {
            load_chunk(kc + 1, s ^ 1);
            asm volatile("cp.async.wait_group 1;" ::: "memory");
        } else {
            asm volatile("cp.async.wait_group 0;" ::: "memory");
        }
        __syncthreads();

#pragma unroll
        for (int ks = 0; ks < KCH; ks += 16) {
            uint32_t ah[4][4], al[4][4], bh[2][4], bl[2][4];
#pragma unroll
            for (int mt = 0; mt < 4; mt++) {
                uint32_t o = (uint32_t)((warpM * 64 + mt * 16 + aRow) * AST + ks + aCol) * 2;
                ldsm4(offAh(s) + o, ah[mt]);
                ldsm4(offAl(s) + o, al[mt]);
            }
#pragma unroll
            for (int np = 0; np < 2; np++) {
                uint32_t o = (uint32_t)((warpN * 32 + np * 16 + bRow) * AST + ks + bCol) * 2;
                ldsm4(offBh(s) + o, bh[np]);
                ldsm4(offBl(s) + o, bl[np]);
            }
#pragma unroll
            for (int mt = 0; mt < 4; mt++)
#pragma unroll
                for (int nt = 0; nt < 4; nt++) {
                    const uint32_t* bhp = &bh[nt >> 1][(nt & 1) * 2];
                    const uint32_t* blp = &bl[nt >> 1][(nt & 1) * 2];
                    mma16816(acc[mt][nt], ah[mt], bhp);
                    mma16816(acc[mt][nt], al[mt], bhp);
                    mma16816(acc[mt][nt], ah[mt], blp);
                }
        }
        __syncthreads();
    }

    // ---- stores: C fp32 (optional), Cxp fp16 (optional), Chi/Clo hi-lo split (optional) ----
#pragma unroll
    for (int mt = 0; mt < 4; mt++) {
        int r0 = mb * 128 + warpM * 64 + mt * 16 + gid;
#pragma unroll
        for (int nt = 0; nt < 4; nt++) {
            int cn = nb * 128 + warpN * 32 + nt * 8 + qid * 2;
            float b0 = bias ? bias[cn] : 0.f;
            float b1 = bias ? bias[cn + 1] : 0.f;
#pragma unroll
            for (int half = 0; half < 2; half++) {
                int r = r0 + half * 8;
                if (r < M) {
                    float v0 = acc[mt][nt][half * 2 + 0] + b0;
                    float v1 = acc[mt][nt][half * 2 + 1] + b1;
                    if (doRelu) { v0 = fmaxf(v0, 0.f); v1 = fmaxf(v1, 0.f); }
                    size_t o = (size_t)r * N + cn;
                    if (C) {
                        C[o] = v0;
                        C[o + 1] = v1;
                    }
                    if (Cxp) {
                        *(__half2*)&Cxp[o] = __floats2half2_rn(v0, v1);
                    }
                    if (Chi) {
                        __half h0 = __float2half(v0);
                        __half h1 = __float2half(v1);
                        __half2 hh, ll;
                        hh.x = h0; hh.y = h1;
                        ll.x = __float2half(v0 - __half2float(h0));
                        ll.y = __float2half(v1 - __half2float(h1));
                        *(__half2*)&Chi[o] = hh;
                        *(__half2*)&Clo[o] = ll;
                    }
                }
            }
        }
    }
}

// ---------------- conversions ----------------
__global__ void k_cvtA(const float* __restrict__ in, __half* __restrict__ hi,
                       __half* __restrict__ lo, int n) {
    int i = blockIdx.x * 256 + threadIdx.x;
    if (i < n) {
        float v = in[i];
        __half h = __float2half(v);
        hi[i] = h;
        lo[i] = __float2half(v - __half2float(h));
    }
}
// ALL weights -> merged K-major fp16 hi/lo buffer in one launch
__global__ void k_cvtAll(const float* __restrict__ enc_w, const float* __restrict__ gat_w,
                         const float* __restrict__ head_w1) {
    int i = blockIdx.x * 256 + threadIdx.x;
    if (i >= WTOT) return;
    float v;
    if (i < ENC_SZ) {                       // enc: [256 N][128 K] <- enc_w[K=128][N=256]
        int n = i >> 7, kk = i & 127;
        v = enc_w[kk * 256 + n];
    } else if (i < HEAD_OFF) {              // gat l: [1024 N][256 K] <- gat_w[l][K=256][N=1024]
        int j = i - GAT_OFF;
        int l = j / GAT_SZ, r = j % GAT_SZ;
        int n = r >> 8, kk = r & 255;
        v = gat_w[(size_t)l * GAT_SZ + kk * 1024 + n];
    } else {                                // head: [512 N][256 K] <- head_w1[4][256][128]
        int j = i - HEAD_OFF;
        int n = j >> 8, kk = j & 255;
        v = head_w1[(n >> 7) * 32768 + kk * 128 + (n & 127)];
    }
    __half h = __float2half(v);
    g_Wh[i] = h;
    g_Wl[i] = __float2half(v - __half2float(h));
}
// v[l][u][d] = sum_j gat_w[l][d, h*256+j] * att[l][h][j];  u = sd*4+h
__global__ void k_vvec(const float* __restrict__ gw, const float* __restrict__ att_s,
                       const float* __restrict__ att_d) {
    int b = blockIdx.x;             // 0..NL*8-1
    int l = b >> 3, u = b & 7;
    int h = u & 3, sd = u >> 2;
    const float* att = (sd ? att_d : att_s) + (l * 4 + h) * 256;
    __shared__ float sa[256];
    sa[threadIdx.x] = att[threadIdx.x];
    __syncthreads();
    int d = threadIdx.x;
    const float* wrow = gw + (size_t)l * 262144 + (size_t)d * 1024 + h * 256;
    float s = 0.f;
#pragma unroll 8
    for (int j = 0; j < 256; j++) s += wrow[j] * sa[j];
    g_vv[(size_t)b * 256 + d] = s;
}
// a_s/a_d from split x (fp32-exact); separate launch = the sync the epilogue needs
__global__ __launch_bounds__(256) void k_asad(const __half* __restrict__ xh,
                                              const __half* __restrict__ xl, int l) {
    int n = blockIdx.x, tid = threadIdx.x, lane = tid & 31, wid = tid >> 5;
    __shared__ float sx[256];
    size_t idx = (size_t)n * 256 + tid;
    sx[tid] = __half2float(xh[idx]) + __half2float(xl[idx]);
    __syncthreads();
    const float* v = g_vv + (size_t)(l * 8 + wid) * 256;
    float s = 0.f;
#pragma unroll
    for (int k = lane; k < 256; k += 32) s += sx[k] * v[k];
    for (int o = 16; o; o >>= 1) s += __shfl_xor_sync(0xffffffffu, s, o);
    if (lane == 0) {
        int h = wid & 3;
        if (wid < 4) g_as[n * 4 + h] = s;
        else g_ad[n * 4 + h] = s;
    }
}

// ---------------- preprocessing ----------------
__global__ void k_zero() {
    int i = blockIdx.x * 256 + threadIdx.x;
    if (i < NN) { g_counts[i] = 0; g_cursor[i] = 0; }
}
__global__ void k_count(const int* __restrict__ dst) {
    int e = blockIdx.x * 256 + threadIdx.x;
    if (e < EE) atomicAdd(&g_counts[dst[e]], 1);
}
__global__ void k_scan() {
    __shared__ int sh[1024];
    int tid = threadIdx.x;
    int carry = 0;
    for (int base = 0; base < NN; base += 1024) {
        int i = base + tid;
        int v = (i < NN) ? g_counts[i] : 0;
        sh[tid] = v;
        __syncthreads();
        for (int off = 1; off < 1024; off <<= 1) {
            int t = (tid >= off) ? sh[tid - off] : 0;
            __syncthreads();
            sh[tid] += t;
            __syncthreads();
        }
        if (i < NN) g_rowptr[i + 1] = carry + sh[tid];
        carry += sh[1023];
        __syncthreads();
    }
    if (tid == 0) g_rowptr[0] = 0;
}
__global__ void k_scatter(const int* __restrict__ src, const int* __restrict__ dst) {
    int e = blockIdx.x * 256 + threadIdx.x;
    if (e < EE) {
        int d = dst[e];
        int pos = g_rowptr[d] + atomicAdd(&g_cursor[d], 1);
        g_csrc[pos] = src[e];
        g_ceid[pos] = e;
    }
}
__global__ void k_wmean(const float* __restrict__ W) {
    __shared__ float red[256];
    int ld = blockIdx.x;
    red[threadIdx.x] = W[(size_t)ld * 256 + threadIdx.x];
    __syncthreads();
    for (int s = 128; s; s >>= 1) {
        if (threadIdx.x < s) red[threadIdx.x] += red[threadIdx.x + s];
        __syncthreads();
    }
    if (threadIdx.x == 0) g_wmean[ld] = red[0] * (1.f / 256.f);
}
__global__ void k_bmean(const float* __restrict__ b) {
    __shared__ float red[256];
    int l = blockIdx.x;
    red[threadIdx.x] = b[l * 256 + threadIdx.x];
    __syncthreads();
    for (int s = 128; s; s >>= 1) {
        if (threadIdx.x < s) red[threadIdx.x] += red[threadIdx.x + s];
        __syncthreads();
    }
    if (threadIdx.x == 0) g_bmean[l] = red[0] * (1.f / 256.f);
}
__global__ void k_cvec(const float* __restrict__ lew, const float* __restrict__ ae) {
    __shared__ float red[256];
    int lh = blockIdx.x;
    size_t off = (size_t)lh * 256 + threadIdx.x;
    red[threadIdx.x] = lew[off] * ae[off];
    __syncthreads();
    for (int s = 128; s; s >>= 1) {
        if (threadIdx.x < s) red[threadIdx.x] += red[threadIdx.x + s];
        __syncthreads();
    }
    if (threadIdx.x == 0) g_cvec[lh] = red[0];
}
__global__ void k_ew3(const float* __restrict__ ea) {
    int warp = threadIdx.x >> 5, lane = threadIdx.x & 31;
    int e = blockIdx.x * 8 + warp;
    if (e >= EE) return;
    const float* row = ea + (size_t)e * EDIM;
    float v0 = row[lane], v1 = row[lane + 32];
    float s0 = v0 * g_wmean[lane] + v1 * g_wmean[lane + 32];
    float s1 = v0 * g_wmean[64 + lane] + v1 * g_wmean[64 + lane + 32];
    float s2 = v0 * g_wmean[128 + lane] + v1 * g_wmean[128 + lane + 32];
    for (int o = 16; o; o >>= 1) {
        s0 += __shfl_down_sync(0xffffffff, s0, o);
        s1 += __shfl_down_sync(0xffffffff, s1, o);
        s2 += __shfl_down_sync(0xffffffff, s2, o);
    }
    if (lane == 0) {
        g_ew[e] = s0 + g_bmean[0];
        g_ew[EE + e] = s1 + g_bmean[1];
        g_ew[2 * EE + e] = s2 + g_bmean[2];
    }
}
__global__ void k_loopw3() {
    int n = blockIdx.x * 256 + threadIdx.x;
    if (n < NN) {
        int b = g_rowptr[n], e = g_rowptr[n + 1];
        float s0 = 0.f, s1 = 0.f, s2 = 0.f;
        for (int p = b; p < e; p++) {
            int id = g_ceid[p];
            s0 += g_ew[id];
            s1 += g_ew[EE + id];
            s2 += g_ew[2 * EE + id];
        }
        float inv = 1.f / fmaxf((float)(e - b), 1.f);
        g_loopw[n] = s0 * inv;
        g_loopw[NN + n] = s1 * inv;
        g_loopw[2 * NN + n] = s2 * inv;
    }
}

// ---------------- fused GAT: online softmax + fp16 gather + LN + residual + split out ----------------
#define GCH 128
__global__ __launch_bounds__(256) void k_gather(float* __restrict__ outF,
                                                __half* __restrict__ xh,
                                                __half* __restrict__ xl,
                                                int l,
                                                const float* __restrict__ gat_b,
                                                const float* __restrict__ ln_g,
                                                const float* __restrict__ ln_b) {
    int n = blockIdx.x, tid = threadIdx.x;
    int lane = tid & 31, wid = tid >> 5;
    int head = tid >> 6, f4 = tid & 63;
    __shared__ int ssrc[GCH];
    __shared__ float slog[GCH][4];
    __shared__ float wt[GCH][4];
    __shared__ float sm4[4], ss4[4], sf4[4];
    __shared__ float sred[1024];
    __shared__ float sw[8];
    __shared__ float sMu, sVar;

    int beg = g_rowptr[n];
    int deg = g_rowptr[n + 1] - beg;

    float4 adv = *(const float4*)&g_ad[n * 4];
    float4 cv = *(const float4*)&g_cvec[l * 4];
    float lw = g_loopw[l * NN + n];
    if (tid < 4) {
        float sl = lrelu(g_as[n * 4 + tid] + g_ad[n * 4 + tid] + lw * g_cvec[l * 4 + tid]);
        sm4[tid] = sl;
        ss4[tid] = 1.f;
    }
    __syncthreads();

    const uint2* xp2 = (const uint2*)g_xph;   // 4 halfs per uint2
    size_t hb = (size_t)head * 64 + f4;
    float4 acc = h4tof4(xp2[(size_t)n * 256 + hb]);   // self, weight 1 at current max

    for (int ch = 0; ch < deg; ch += GCH) {
        int cnt = min(GCH, deg - ch);
        if (tid < cnt) {
            int p = beg + ch + tid;
            int s0 = g_csrc[p];
            float w = g_ew[l * EE + g_ceid[p]];
            ssrc[tid] = s0;
            float4 as4 = *(const float4*)&g_as[s0 * 4];
            slog[tid][0] = lrelu(as4.x + adv.x + w * cv.x);
            slog[tid][1] = lrelu(as4.y + adv.y + w * cv.y);
            slog[tid][2] = lrelu(as4.z + adv.z + w * cv.z);
            slog[tid][3] = lrelu(as4.w + adv.w + w * cv.w);
        }
        __syncthreads();
        if (wid < 4) {
            int h = wid;
            float cm = -1e30f;
            for (int j = lane; j < cnt; j += 32) cm = fmaxf(cm, slog[j][h]);
            for (int o = 16; o; o >>= 1) cm = fmaxf(cm, __shfl_xor_sync(0xffffffff, cm, o));
            float mold = sm4[h];
            float mnew = fmaxf(mold, cm);
            float fac = expf(mold - mnew);
            float cs = 0.f;
            for (int j = lane; j < cnt; j += 32) {
                float p = expf(slog[j][h] - mnew);
                wt[j][h] = p;
                cs += p;
            }
            for (int o = 16; o; o >>= 1) cs += __shfl_xor_sync(0xffffffff, cs, o);
            if (lane == 0) {
                ss4[h] = ss4[h] * fac + cs;
                sm4[h] = mnew;
                sf4[h] = fac;
            }
        }
        __syncthreads();
        float f = sf4[head];
        acc.x *= f; acc.y *= f; acc.z *= f; acc.w *= f;
        int j = 0;
        for (; j + 4 <= cnt; j += 4) {
            float a0 = wt[j][head], a1 = wt[j + 1][head];
            float a2 = wt[j + 2][head], a3 = wt[j + 3][head];
            float4 v0 = h4tof4(xp2[(size_t)ssrc[j] * 256 + hb]);
            float4 v1 = h4tof4(xp2[(size_t)ssrc[j + 1] * 256 + hb]);
            float4 v2 = h4tof4(xp2[(size_t)ssrc[j + 2] * 256 + hb]);
            float4 v3 = h4tof4(xp2[(size_t)ssrc[j + 3] * 256 + hb]);
            acc.x += a0 * v0.x + a1 * v1.x + a2 * v2.x + a3 * v3.x;
            acc.y += a0 * v0.y + a1 * v1.y + a2 * v2.y + a3 * v3.y;
            acc.z += a0 * v0.z + a1 * v1.z + a2 * v2.z + a3 * v3.z;
            acc.w += a0 * v0.w + a1 * v1.w + a2 * v2.w + a3 * v3.w;
        }
        for (; j < cnt; j++) {
            float a = wt[j][head];
            float4 v = h4tof4(xp2[(size_t)ssrc[j] * 256 + hb]);
            acc.x += a * v.x;
            acc.y += a * v.y;
            acc.z += a * v.z;
            acc.w += a * v.w;
        }
        __syncthreads();   // before smem reuse next chunk
    }

    float inv = 0.25f / ss4[head];
    acc.x *= inv; acc.y *= inv; acc.z *= inv; acc.w *= inv;
    *(float4*)&sred[head * 256 + f4 * 4] = acc;
    __syncthreads();

    float h = sred[tid] + sred[256 + tid] + sred[512 + tid] + sred[768 + tid] + gat_b[tid];

    float v = h;
    for (int o = 16; o; o >>= 1) v += __shfl_xor_sync(0xffffffff, v, o);
    if (lane == 0) sw[wid] = v;
    __syncthreads();
    if (tid == 0) {
        float t = sw[0] + sw[1] + sw[2] + sw[3] + sw[4] + sw[5] + sw[6] + sw[7];
        sMu = t * (1.f / 256.f);
    }
    __syncthreads();
    float df = h - sMu;
    v = df * df;
    for (int o = 16; o; o >>= 1) v += __shfl_xor_sync(0xffffffff, v, o);
    __syncthreads();
    if (lane == 0) sw[wid] = v;
    __syncthreads();
    if (tid == 0) {
        float t = sw[0] + sw[1] + sw[2] + sw[3] + sw[4] + sw[5] + sw[6] + sw[7];
        sVar = t * (1.f / 256.f);
    }
    __syncthreads();
    float y = ln_g[tid] * df * rsqrtf(sVar + 1e-5f) + ln_b[tid];
    size_t idx = (size_t)n * 256 + tid;
    // residual from exact fp16 hi/lo reconstruction (error ~2^-22)
    float xr = __half2float(xh[idx]) + __half2float(xl[idx]);
    float o = fmaxf(xr + y, 0.f);
    if (outF) outF[idx] = o;
    __half hh = __float2half(o);
    xh[idx] = hh;
    xl[idx] = __float2half(o - __half2float(hh));
}

// ---------------- prediction heads epilogue ----------------
__global__ void k_headout(const float* __restrict__ w2, const float* __restrict__ b2,
                          float* __restrict__ out) {
    int n = blockIdx.x;
    int k = threadIdx.x >> 5, lane = threadIdx.x & 31;
    const float* hr = g_hmid + (size_t)n * 512 + k * 128;
    const float* w = w2 + k * 128;
    float s = 0.f;
    for (int i = lane; i < 128; i += 32) s += hr[i] * w[i];
    for (int o = 16; o; o >>= 1) s += __shfl_down_sync(0xffffffff, s, o);
    if (lane == 0) {
        float v = s + b2[k];
        if (k == 0 || k == 3) v = 1.f / (1.f + expf(-v));
        out[(size_t)k * NN + n] = v;
    }
}

// ---------------- launch ----------------
extern "C" void kernel_launch(void* const* d_in, const int* in_sizes, int n_in,
                              void* d_out, int out_size) {
    const float* node_features = (const float*)d_in[0];
    const float* edge_attr     = (const float*)d_in[1];
    const float* enc_w         = (const float*)d_in[2];
    const float* enc_b         = (const float*)d_in[3];
    const float* edge_enc_w    = (const float*)d_in[4];
    const float* edge_enc_b    = (const float*)d_in[5];
    const float* gat_w         = (const float*)d_in[6];
    const float* att_src       = (const float*)d_in[7];
    const float* att_dst       = (const float*)d_in[8];
    const float* att_edge      = (const float*)d_in[9];
    const float* lin_edge_w    = (const float*)d_in[10];
    const float* gat_b         = (const float*)d_in[11];
    const float* ln_g          = (const float*)d_in[12];
    const float* ln_b          = (const float*)d_in[13];
    const float* head_w1       = (const float*)d_in[14];
    const float* head_b1       = (const float*)d_in[15];
    const float* head_w2       = (const float*)d_in[16];
    const float* head_b2       = (const float*)d_in[17];
    const int*   src           = (const int*)d_in[18];
    const int*   dst           = src + EE;
    float* out = (float*)d_out;

    float* phmid;
    __half *pxph, *pAh, *pAl, *pXh, *pXl, *pWh, *pWl;
    cudaGetSymbolAddress((void**)&pxph, g_xph);
    cudaGetSymbolAddress((void**)&phmid, g_hmid);
    cudaGetSymbolAddress((void**)&pAh, g_Ah);
    cudaGetSymbolAddress((void**)&pAl, g_Al);
    cudaGetSymbolAddress((void**)&pXh, g_Xh);
    cudaGetSymbolAddress((void**)&pXl, g_Xl);
    cudaGetSymbolAddress((void**)&pWh, g_Wh);
    cudaGetSymbolAddress((void**)&pWl, g_Wl);

    cudaFuncSetAttribute(k_mma, cudaFuncAttributeMaxDynamicSharedMemorySize, GEMM_SMEM);

    const int MT = (NN + 127) / 128;  // 157 M-tiles

    // ---- graph preprocessing (dst-CSR) + per-layer constants + all weight conversions ----
    k_zero<<<(NN + 255) / 256, 256>>>();
    k_count<<<(EE + 255) / 256, 256>>>(dst);
    k_scan<<<1, 1024>>>();
    k_scatter<<<(EE + 255) / 256, 256>>>(src, dst);
    k_wmean<<<NL * EDIM, 256>>>(edge_enc_w);
    k_bmean<<<NL, 256>>>(edge_enc_b);
    k_cvec<<<NL * NHEADS, 256>>>(lin_edge_w, att_edge);
    k_ew3<<<(EE + 7) / 8, 256>>>(edge_attr);
    k_loopw3<<<(NN + 255) / 256, 256>>>();
    k_vvec<<<NL * 8, 256>>>(gat_w, att_src, att_dst);
    k_cvtAll<<<(WTOT + 255) / 256, 256>>>(enc_w, gat_w, head_w1);
    k_cvtA<<<(NN * NDIM + 255) / 256, 256>>>(node_features, pAh, pAl, NN * NDIM);

    // ---- encoder: x = relu(nf @ enc_w + enc_b) -> fp16 hi/lo split only ----
    k_mma<<<dim3(HD / 128, MT), 256, GEMM_SMEM>>>(pAh, pAl, pWh + ENC_OFF, pWl + ENC_OFF,
                                                  nullptr, nullptr, pXh, pXl,
                                                  NN, HD, NDIM, enc_b, 1);
    k_asad<<<NN, 256>>>(pXh, pXl, 0);

    // ---- 3 GAT layers ----
    for (int l = 0; l < NL; l++) {
        float* XO = (l == 2) ? out + 4 * NN : nullptr;

        // xp = x @ gat_w[l] -> fp16 xp
        k_mma<<<dim3(1024 / 128, MT), 256, GEMM_SMEM>>>(
            pXh, pXl, pWh + GAT_OFF + l * GAT_SZ, pWl + GAT_OFF + l * GAT_SZ,
            nullptr, pxph, nullptr, nullptr, NN, 1024, HD, nullptr, 0);

        k_gather<<<NN, 256>>>(XO, pXh, pXl, l,
                              gat_b + l * 256, ln_g + l * 256, ln_b + l * 256);
        if (l < 2) k_asad<<<NN, 256>>>(pXh, pXl, l + 1);
    }
    // emb in out[4*NN ..]; fp16 hi/lo split in pXh/pXl

    // ---- combined prediction heads: hmid = relu(emb @ [W1_0|W1_1|W1_2|W1_3] + b1) ----
    k_mma<<<dim3(512 / 128, MT), 256, GEMM_SMEM>>>(pXh, pXl, pWh + HEAD_OFF, pWl + HEAD_OFF,
                                                   phmid, nullptr, nullptr, nullptr,
                                                   NN, 512, HD, head_b1, 1);
    k_headout<<<NN, 128>>>(head_w2, head_b2, out);
}

// round 15
// speedup vs baseline: 1.0788x; 1.0788x over previous
#include <cuda_runtime.h>
#include <cuda_fp16.h>
#include <cstdint>
#include <math.h>

#define NN 20000
#define EE 200000
#define HD 256
#define NHEADS 4
#define NDIM 128
#define EDIM 64
#define NL 3

// ---------------- scratch (static device globals; no runtime allocation) ----------------
__device__ __half g_xph[(size_t)NN * NHEADS * HD];  // xp in fp16 [N,1024]
__device__ float g_as [NN * NHEADS];
__device__ float g_ad [NN * NHEADS];
__device__ float g_ew [NL * EE];
__device__ float g_loopw[NL * NN];
__device__ int   g_counts[NN];
__device__ int   g_cursor[NN];
__device__ int   g_rowptr[NN + 1];
__device__ int   g_csrc[EE];
__device__ int   g_ceid[EE];
__device__ float g_hmid[(size_t)NN * 512];
__device__ float g_wmean[NL * EDIM];
__device__ float g_bmean[NL];
__device__ float g_cvec [NL * NHEADS];
// fp16 hi/lo split buffers (A = activations, B = weights)
__device__ __half g_Ah[(size_t)NN * HD];
__device__ __half g_Al[(size_t)NN * HD];
__device__ __half g_Xh[(size_t)NN * HD];    // activation x split (exact fp32 = hi+lo)
__device__ __half g_Xl[(size_t)NN * HD];
__device__ __half g_Bh[1024 * 256];
__device__ __half g_Bl[1024 * 256];

// ---------------- helpers ----------------
__device__ __forceinline__ float lrelu(float x) { return fmaxf(x, 0.2f * x); }

__device__ __forceinline__ void mma16816(float* c, const uint32_t* a, const uint32_t* b) {
    asm volatile(
        "mma.sync.aligned.m16n8k16.row.col.f32.f16.f16.f32 "
        "{%0,%1,%2,%3}, {%4,%5,%6,%7}, {%8,%9}, {%0,%1,%2,%3};"
        : "+f"(c[0]), "+f"(c[1]), "+f"(c[2]), "+f"(c[3])
        : "r"(a[0]), "r"(a[1]), "r"(a[2]), "r"(a[3]), "r"(b[0]), "r"(b[1]));
}
__device__ __forceinline__ void ldsm4(uint32_t addr, uint32_t* r) {
    asm volatile("ldmatrix.sync.aligned.m8n8.x4.shared.b16 {%0,%1,%2,%3}, [%4];"
                 : "=r"(r[0]), "=r"(r[1]), "=r"(r[2]), "=r"(r[3]) : "r"(addr));
}
__device__ __forceinline__ void cpa16z(uint32_t dst, const void* src, int sz) {
    asm volatile("cp.async.cg.shared.global [%0], [%1], 16, %2;"
                 :: "r"(dst), "l"(src), "r"(sz));
}
__device__ __forceinline__ float4 h4tof4(uint2 u) {
    __half2 a = *(__half2*)&u.x, b = *(__half2*)&u.y;
    float2 fa = __half22float2(a), fb = __half22float2(b);
    return make_float4(fa.x, fa.y, fb.x, fb.y);
}

// ---------------- fp16x3 GEMM (A,B both hi/lo split), double-buffered cp.async ----------------
// C = A@B; error ~2^-21 (dropped al*bl). Block 128x128, 8 warps, warp 64x32, K-chunk 32.
#define KCH 32
#define AST 40                       // smem row stride fp16 (80B: conflict-free ldmatrix)
#define STG (128 * AST)
#define GEMM_SMEM (8 * STG * 2)      // 81920 bytes
__global__ __launch_bounds__(256, 2) void k_mma(
    const __half* __restrict__ Ah, const __half* __restrict__ Al,
    const __half* __restrict__ Bh, const __half* __restrict__ Bl,
    float* __restrict__ C, __half* __restrict__ Cxp,
    __half* __restrict__ Chi, __half* __restrict__ Clo,
    int M, int N, int K, const float* __restrict__ bias, int doRelu,
    const float* __restrict__ attS, const float* __restrict__ attD) {
    extern __shared__ __half sm[];
    __shared__ float sAS[128], sAD[128];
    uint32_t base = (uint32_t)__cvta_generic_to_shared(sm);

    int tid = threadIdx.x, lane = tid & 31, wid = tid >> 5;
    int nb = blockIdx.x, mb = blockIdx.y;
    int warpM = wid >> 2, warpN = wid & 3;
    int gid = lane >> 2, qid = lane & 3;
    int NC = K / KCH;

    auto offAh = [&](int s) { return base + (uint32_t)(4 * s) * STG * 2; };
    auto offAl = [&](int s) { return base + (uint32_t)(4 * s + 1) * STG * 2; };
    auto offBh = [&](int s) { return base + (uint32_t)(4 * s + 2) * STG * 2; };
    auto offBl = [&](int s) { return base + (uint32_t)(4 * s + 3) * STG * 2; };

    auto load_chunk = [&](int kc, int s) {
        int k0 = kc * KCH;
#pragma unroll
        for (int i = tid; i < 512; i += 256) {
            int row = i >> 2, c = i & 3;
            uint32_t so = (uint32_t)(row * AST + c * 8) * 2;
            int gr = mb * 128 + row;
            int sz = (gr < M) ? 16 : 0;
            int grc = (gr < M) ? gr : (M - 1);
            cpa16z(offAh(s) + so, Ah + (size_t)grc * K + k0 + c * 8, sz);
            cpa16z(offAl(s) + so, Al + (size_t)grc * K + k0 + c * 8, sz);
            int gn = nb * 128 + row;
            cpa16z(offBh(s) + so, Bh + (size_t)gn * K + k0 + c * 8, 16);
            cpa16z(offBl(s) + so, Bl + (size_t)gn * K + k0 + c * 8, 16);
        }
        asm volatile("cp.async.commit_group;");
    };

    float acc[4][4][4];
#pragma unroll
    for (int i = 0; i < 4; i++)
#pragma unroll
        for (int j = 0; j < 4; j++)
#pragma unroll
            for (int k = 0; k < 4; k++) acc[i][j][k] = 0.f;

    int aRow = (lane & 15), aCol = (lane >> 4) * 8;
    int bRow = (lane & 7) + ((lane >> 4) << 3), bCol = ((lane >> 3) & 1) * 8;

    load_chunk(0, 0);

    for (int kc = 0; kc < NC; kc++) {
        int s = kc & 1;
        if (kc + 1 < NC) {
            load_chunk(kc + 1, s ^ 1);
            asm volatile("cp.async.wait_group 1;" ::: "memory");
        } else {
            asm volatile("cp.async.wait_group 0;" ::: "memory");
        }
        __syncthreads();

#pragma unroll
        for (int ks = 0; ks < KCH; ks += 16) {
            uint32_t ah[4][4], al[4][4], bh[2][4], bl[2][4];
#pragma unroll
            for (int mt = 0; mt < 4; mt++) {
                uint32_t o = (uint32_t)((warpM * 64 + mt * 16 + aRow) * AST + ks + aCol) * 2;
                ldsm4(offAh(s) + o, ah[mt]);
                ldsm4(offAl(s) + o, al[mt]);
            }
#pragma unroll
            for (int np = 0; np < 2; np++) {
                uint32_t o = (uint32_t)((warpN * 32 + np * 16 + bRow) * AST + ks + bCol) * 2;
                ldsm4(offBh(s) + o, bh[np]);
                ldsm4(offBl(s) + o, bl[np]);
            }
#pragma unroll
            for (int mt = 0; mt < 4; mt++)
#pragma unroll
                for (int nt = 0; nt < 4; nt++) {
                    const uint32_t* bhp = &bh[nt >> 1][(nt & 1) * 2];
                    const uint32_t* blp = &bl[nt >> 1][(nt & 1) * 2];
                    mma16816(acc[mt][nt], ah[mt], bhp);
                    mma16816(acc[mt][nt], al[mt], bhp);
                    mma16816(acc[mt][nt], ah[mt], blp);
                }
        }
        __syncthreads();
    }

    // ---- fused attention dots from exact fp32 accumulators (CTA covers 1 head) ----
    if (attS) {
        if (tid < 128) { sAS[tid] = 0.f; sAD[tid] = 0.f; }
        __syncthreads();
        float avS[8], avD[8];
#pragma unroll
        for (int nt = 0; nt < 4; nt++) {
            int cn = nb * 128 + warpN * 32 + nt * 8 + qid * 2;
            avS[nt * 2] = attS[cn];
            avS[nt * 2 + 1] = attS[cn + 1];
            avD[nt * 2] = attD[cn];
            avD[nt * 2 + 1] = attD[cn + 1];
        }
#pragma unroll
        for (int mt = 0; mt < 4; mt++)
#pragma unroll
            for (int half = 0; half < 2; half++) {
                float sp = 0.f, dp = 0.f;
#pragma unroll
                for (int nt = 0; nt < 4; nt++) {
                    float a0 = acc[mt][nt][half * 2], a1 = acc[mt][nt][half * 2 + 1];
                    sp += a0 * avS[nt * 2] + a1 * avS[nt * 2 + 1];
                    dp += a0 * avD[nt * 2] + a1 * avD[nt * 2 + 1];
                }
                sp += __shfl_xor_sync(0xffffffffu, sp, 1);
                sp += __shfl_xor_sync(0xffffffffu, sp, 2);
                dp += __shfl_xor_sync(0xffffffffu, dp, 1);
                dp += __shfl_xor_sync(0xffffffffu, dp, 2);
                if (qid == 0) {
                    int rl = warpM * 64 + mt * 16 + gid + half * 8;
                    atomicAdd(&sAS[rl], sp);
                    atomicAdd(&sAD[rl], dp);
                }
            }
        __syncthreads();
        if (tid < 128) {
            int r = mb * 128 + tid;
            if (r < M) {
                int h = nb >> 1;   // 128 cols/CTA, 256 cols/head
                atomicAdd(&g_as[r * 4 + h], sAS[tid]);
                atomicAdd(&g_ad[r * 4 + h], sAD[tid]);
            }
        }
    }

    // ---- stores: C fp32 (optional), Cxp fp16 (optional), Chi/Clo hi-lo split (optional) ----
#pragma unroll
    for (int mt = 0; mt < 4; mt++) {
        int r0 = mb * 128 + warpM * 64 + mt * 16 + gid;
#pragma unroll
        for (int nt = 0; nt < 4; nt++) {
            int cn = nb * 128 + warpN * 32 + nt * 8 + qid * 2;
            float b0 = bias ? bias[cn] : 0.f;
            float b1 = bias ? bias[cn + 1] : 0.f;
#pragma unroll
            for (int half = 0; half < 2; half++) {
                int r = r0 + half * 8;
                if (r < M) {
                    float v0 = acc[mt][nt][half * 2 + 0] + b0;
                    float v1 = acc[mt][nt][half * 2 + 1] + b1;
                    if (doRelu) { v0 = fmaxf(v0, 0.f); v1 = fmaxf(v1, 0.f); }
                    size_t o = (size_t)r * N + cn;
                    if (C) {
                        C[o] = v0;
                        C[o + 1] = v1;
                    }
                    if (Cxp) {
                        *(__half2*)&Cxp[o] = __floats2half2_rn(v0, v1);
                    }
                    if (Chi) {
                        __half h0 = __float2half(v0);
                        __half h1 = __float2half(v1);
                        __half2 hh, ll;
                        hh.x = h0; hh.y = h1;
                        ll.x = __float2half(v0 - __half2float(h0));
                        ll.y = __float2half(v1 - __half2float(h1));
                        *(__half2*)&Chi[o] = hh;
                        *(__half2*)&Clo[o] = ll;
                    }
                }
            }
        }
    }
}

// ---------------- fp16 hi/lo conversions ----------------
__global__ void k_cvtA(const float* __restrict__ in, __half* __restrict__ hi,
                       __half* __restrict__ lo, int n) {
    int i = blockIdx.x * 256 + threadIdx.x;
    if (i < n) {
        float v = in[i];
        __half h = __float2half(v);
        hi[i] = h;
        lo[i] = __float2half(v - __half2float(h));
    }
}
// weights [K,N] fp32 -> [N,K] fp16 hi/lo (transpose; K-contiguous)
__global__ void k_cvtBT(const float* __restrict__ in, __half* __restrict__ hi,
                        __half* __restrict__ lo, int K, int N) {
    int i = blockIdx.x * 256 + threadIdx.x;
    if (i < K * N) {
        int kk = i / N, n = i % N;
        float v = in[i];
        __half h = __float2half(v);
        size_t o = (size_t)n * K + kk;
        hi[o] = h;
        lo[o] = __float2half(v - __half2float(h));
    }
}
// head_w1 [4][256][128] -> combined B [512][256] K-contiguous fp16 split
__global__ void k_cvtHW(const float* __restrict__ in, __half* __restrict__ hi,
                        __half* __restrict__ lo) {
    int i = blockIdx.x * 256 + threadIdx.x;   // over 512*256
    if (i < 512 * 256) {
        int n = i >> 8, kk = i & 255;
        float v = in[(n >> 7) * 32768 + kk * 128 + (n & 127)];
        __half h = __float2half(v);
        hi[i] = h;
        lo[i] = __float2half(v - __half2float(h));
    }
}
__global__ void k_zeroAS() {
    int i = blockIdx.x * 256 + threadIdx.x;
    if (i < NN * 4) { g_as[i] = 0.f; g_ad[i] = 0.f; }
}

// ---------------- preprocessing ----------------
__global__ void k_zero() {
    int i = blockIdx.x * 256 + threadIdx.x;
    if (i < NN) { g_counts[i] = 0; g_cursor[i] = 0; }
}
__global__ void k_count(const int* __restrict__ dst) {
    int e = blockIdx.x * 256 + threadIdx.x;
    if (e < EE) atomicAdd(&g_counts[dst[e]], 1);
}
__global__ void k_scan() {
    __shared__ int sh[1024];
    int tid = threadIdx.x;
    int carry = 0;
    for (int base = 0; base < NN; base += 1024) {
        int i = base + tid;
        int v = (i < NN) ? g_counts[i] : 0;
        sh[tid] = v;
        __syncthreads();
        for (int off = 1; off < 1024; off <<= 1) {
            int t = (tid >= off) ? sh[tid - off] : 0;
            __syncthreads();
            sh[tid] += t;
            __syncthreads();
        }
        if (i < NN) g_rowptr[i + 1] = carry + sh[tid];
        carry += sh[1023];
        __syncthreads();
    }
    if (tid == 0) g_rowptr[0] = 0;
}
__global__ void k_scatter(const int* __restrict__ src, const int* __restrict__ dst) {
    int e = blockIdx.x * 256 + threadIdx.x;
    if (e < EE) {
        int d = dst[e];
        int pos = g_rowptr[d] + atomicAdd(&g_cursor[d], 1);
        g_csrc[pos] = src[e];
        g_ceid[pos] = e;
    }
}
__global__ void k_wmean(const float* __restrict__ W) {
    __shared__ float red[256];
    int ld = blockIdx.x;
    red[threadIdx.x] = W[(size_t)ld * 256 + threadIdx.x];
    __syncthreads();
    for (int s = 128; s; s >>= 1) {
        if (threadIdx.x < s) red[threadIdx.x] += red[threadIdx.x + s];
        __syncthreads();
    }
    if (threadIdx.x == 0) g_wmean[ld] = red[0] * (1.f / 256.f);
}
__global__ void k_bmean(const float* __restrict__ b) {
    __shared__ float red[256];
    int l = blockIdx.x;
    red[threadIdx.x] = b[l * 256 + threadIdx.x];
    __syncthreads();
    for (int s = 128; s; s >>= 1) {
        if (threadIdx.x < s) red[threadIdx.x] += red[threadIdx.x + s];
        __syncthreads();
    }
    if (threadIdx.x == 0) g_bmean[l] = red[0] * (1.f / 256.f);
}
__global__ void k_cvec(const float* __restrict__ lew, const float* __restrict__ ae) {
    __shared__ float red[256];
    int lh = blockIdx.x;
    size_t off = (size_t)lh * 256 + threadIdx.x;
    red[threadIdx.x] = lew[off] * ae[off];
    __syncthreads();
    for (int s = 128; s; s >>= 1) {
        if (threadIdx.x < s) red[threadIdx.x] += red[threadIdx.x + s];
        __syncthreads();
    }
    if (threadIdx.x == 0) g_cvec[lh] = red[0];
}
__global__ void k_ew3(const float* __restrict__ ea) {
    int warp = threadIdx.x >> 5, lane = threadIdx.x & 31;
    int e = blockIdx.x * 8 + warp;
    if (e >= EE) return;
    const float* row = ea + (size_t)e * EDIM;
    float v0 = row[lane], v1 = row[lane + 32];
    float s0 = v0 * g_wmean[lane] + v1 * g_wmean[lane + 32];
    float s1 = v0 * g_wmean[64 + lane] + v1 * g_wmean[64 + lane + 32];
    float s2 = v0 * g_wmean[128 + lane] + v1 * g_wmean[128 + lane + 32];
    for (int o = 16; o; o >>= 1) {
        s0 += __shfl_down_sync(0xffffffff, s0, o);
        s1 += __shfl_down_sync(0xffffffff, s1, o);
        s2 += __shfl_down_sync(0xffffffff, s2, o);
    }
    if (lane == 0) {
        g_ew[e] = s0 + g_bmean[0];
        g_ew[EE + e] = s1 + g_bmean[1];
        g_ew[2 * EE + e] = s2 + g_bmean[2];
    }
}
__global__ void k_loopw3() {
    int n = blockIdx.x * 256 + threadIdx.x;
    if (n < NN) {
        int b = g_rowptr[n], e = g_rowptr[n + 1];
        float s0 = 0.f, s1 = 0.f, s2 = 0.f;
        for (int p = b; p < e; p++) {
            int id = g_ceid[p];
            s0 += g_ew[id];
            s1 += g_ew[EE + id];
            s2 += g_ew[2 * EE + id];
        }
        float inv = 1.f / fmaxf((float)(e - b), 1.f);
        g_loopw[n] = s0 * inv;
        g_loopw[NN + n] = s1 * inv;
        g_loopw[2 * NN + n] = s2 * inv;
    }
}

// ---------------- fused GAT: online softmax + fp16 gather + LN + residual + split out ----------------
#define GCH 128
__global__ __launch_bounds__(256) void k_gather(float* __restrict__ outF,
                                                __half* __restrict__ xh,
                                                __half* __restrict__ xl,
                                                int l,
                                                const float* __restrict__ gat_b,
                                                const float* __restrict__ ln_g,
                                                const float* __restrict__ ln_b) {
    int n = blockIdx.x, tid = threadIdx.x;
    int lane = tid & 31, wid = tid >> 5;
    int head = tid >> 6, f4 = tid & 63;
    __shared__ int ssrc[GCH];
    __shared__ float slog[GCH][4];
    __shared__ float wt[GCH][4];
    __shared__ float sm4[4], ss4[4], sf4[4];
    __shared__ float sred[1024];
    __shared__ float sw[8];
    __shared__ float sMu, sVar;

    int beg = g_rowptr[n];
    int deg = g_rowptr[n + 1] - beg;

    float4 adv = *(const float4*)&g_ad[n * 4];
    float4 cv = *(const float4*)&g_cvec[l * 4];
    float lw = g_loopw[l * NN + n];
    if (tid < 4) {
        float sl = lrelu(g_as[n * 4 + tid] + g_ad[n * 4 + tid] + lw * g_cvec[l * 4 + tid]);
        sm4[tid] = sl;
        ss4[tid] = 1.f;
    }
    __syncthreads();

    const uint2* xp2 = (const uint2*)g_xph;   // 4 halfs per uint2
    size_t hb = (size_t)head * 64 + f4;
    float4 acc = h4tof4(xp2[(size_t)n * 256 + hb]);   // self, weight 1 at current max

    for (int ch = 0; ch < deg; ch += GCH) {
        int cnt = min(GCH, deg - ch);
        if (tid < cnt) {
            int p = beg + ch + tid;
            int s0 = g_csrc[p];
            float w = g_ew[l * EE + g_ceid[p]];
            ssrc[tid] = s0;
            float4 as4 = *(const float4*)&g_as[s0 * 4];
            slog[tid][0] = lrelu(as4.x + adv.x + w * cv.x);
            slog[tid][1] = lrelu(as4.y + adv.y + w * cv.y);
            slog[tid][2] = lrelu(as4.z + adv.z + w * cv.z);
            slog[tid][3] = lrelu(as4.w + adv.w + w * cv.w);
        }
        __syncthreads();
        if (wid < 4) {
            int h = wid;
            float cm = -1e30f;
            for (int j = lane; j < cnt; j += 32) cm = fmaxf(cm, slog[j][h]);
            for (int o = 16; o; o >>= 1) cm = fmaxf(cm, __shfl_xor_sync(0xffffffff, cm, o));
            float mold = sm4[h];
            float mnew = fmaxf(mold, cm);
            float fac = expf(mold - mnew);
            float cs = 0.f;
            for (int j = lane; j < cnt; j += 32) {
                float p = expf(slog[j][h] - mnew);
                wt[j][h] = p;
                cs += p;
            }
            for (int o = 16; o; o >>= 1) cs += __shfl_xor_sync(0xffffffff, cs, o);
            if (lane == 0) {
                ss4[h] = ss4[h] * fac + cs;
                sm4[h] = mnew;
                sf4[h] = fac;
            }
        }
        __syncthreads();
        float f = sf4[head];
        acc.x *= f; acc.y *= f; acc.z *= f; acc.w *= f;
        int j = 0;
        for (; j + 4 <= cnt; j += 4) {
            float a0 = wt[j][head], a1 = wt[j + 1][head];
            float a2 = wt[j + 2][head], a3 = wt[j + 3][head];
            float4 v0 = h4tof4(xp2[(size_t)ssrc[j] * 256 + hb]);
            float4 v1 = h4tof4(xp2[(size_t)ssrc[j + 1] * 256 + hb]);
            float4 v2 = h4tof4(xp2[(size_t)ssrc[j + 2] * 256 + hb]);
            float4 v3 = h4tof4(xp2[(size_t)ssrc[j + 3] * 256 + hb]);
            acc.x += a0 * v0.x + a1 * v1.x + a2 * v2.x + a3 * v3.x;
            acc.y += a0 * v0.y + a1 * v1.y + a2 * v2.y + a3 * v3.y;
            acc.z += a0 * v0.z + a1 * v1.z + a2 * v2.z + a3 * v3.z;
            acc.w += a0 * v0.w + a1 * v1.w + a2 * v2.w + a3 * v3.w;
        }
        for (; j < cnt; j++) {
            float a = wt[j][head];
            float4 v = h4tof4(xp2[(size_t)ssrc[j] * 256 + hb]);
            acc.x += a * v.x;
            acc.y += a * v.y;
            acc.z += a * v.z;
            acc.w += a * v.w;
        }
        __syncthreads();   // before smem reuse next chunk
    }

    float inv = 0.25f / ss4[head];
    acc.x *= inv; acc.y *= inv; acc.z *= inv; acc.w *= inv;
    *(float4*)&sred[head * 256 + f4 * 4] = acc;
    __syncthreads();

    float h = sred[tid] + sred[256 + tid] + sred[512 + tid] + sred[768 + tid] + gat_b[tid];

    float v = h;
    for (int o = 16; o; o >>= 1) v += __shfl_xor_sync(0xffffffff, v, o);
    if (lane == 0) sw[wid] = v;
    __syncthreads();
    if (tid == 0) {
        float t = sw[0] + sw[1] + sw[2] + sw[3] + sw[4] + sw[5] + sw[6] + sw[7];
        sMu = t * (1.f / 256.f);
    }
    __syncthreads();
    float df = h - sMu;
    v = df * df;
    for (int o = 16; o; o >>= 1) v += __shfl_xor_sync(0xffffffff, v, o);
    __syncthreads();
    if (lane == 0) sw[wid] = v;
    __syncthreads();
    if (tid == 0) {
        float t = sw[0] + sw[1] + sw[2] + sw[3] + sw[4] + sw[5] + sw[6] + sw[7];
        sVar = t * (1.f / 256.f);
    }
    __syncthreads();
    float y = ln_g[tid] * df * rsqrtf(sVar + 1e-5f) + ln_b[tid];
    size_t idx = (size_t)n * 256 + tid;
    // residual from exact fp16 hi/lo reconstruction (error ~2^-22)
    float xr = __half2float(xh[idx]) + __half2float(xl[idx]);
    float o = fmaxf(xr + y, 0.f);
    if (outF) outF[idx] = o;
    __half hh = __float2half(o);
    xh[idx] = hh;
    xl[idx] = __float2half(o - __half2float(hh));
}

// ---------------- prediction heads epilogue ----------------
__global__ void k_headout(const float* __restrict__ w2, const float* __restrict__ b2,
                          float* __restrict__ out) {
    int n = blockIdx.x;
    int k = threadIdx.x >> 5, lane = threadIdx.x & 31;
    const float* hr = g_hmid + (size_t)n * 512 + k * 128;
    const float* w = w2 + k * 128;
    float s = 0.f;
    for (int i = lane; i < 128; i += 32) s += hr[i] * w[i];
    for (int o = 16; o; o >>= 1) s += __shfl_down_sync(0xffffffff, s, o);
    if (lane == 0) {
        float v = s + b2[k];
        if (k == 0 || k == 3) v = 1.f / (1.f + expf(-v));
        out[(size_t)k * NN + n] = v;
    }
}

// ---------------- launch ----------------
extern "C" void kernel_launch(void* const* d_in, const int* in_sizes, int n_in,
                              void* d_out, int out_size) {
    const float* node_features = (const float*)d_in[0];
    const float* edge_attr     = (const float*)d_in[1];
    const float* enc_w         = (const float*)d_in[2];
    const float* enc_b         = (const float*)d_in[3];
    const float* edge_enc_w    = (const float*)d_in[4];
    const float* edge_enc_b    = (const float*)d_in[5];
    const float* gat_w         = (const float*)d_in[6];
    const float* att_src       = (const float*)d_in[7];
    const float* att_dst       = (const float*)d_in[8];
    const float* att_edge      = (const float*)d_in[9];
    const float* lin_edge_w    = (const float*)d_in[10];
    const float* gat_b         = (const float*)d_in[11];
    const float* ln_g          = (const float*)d_in[12];
    const float* ln_b          = (const float*)d_in[13];
    const float* head_w1       = (const float*)d_in[14];
    const float* head_b1       = (const float*)d_in[15];
    const float* head_w2       = (const float*)d_in[16];
    const float* head_b2       = (const float*)d_in[17];
    const int*   src           = (const int*)d_in[18];
    const int*   dst           = src + EE;
    float* out = (float*)d_out;

    float* phmid;
    __half *pxph, *pAh, *pAl, *pXh, *pXl, *pBh, *pBl;
    cudaGetSymbolAddress((void**)&pxph, g_xph);
    cudaGetSymbolAddress((void**)&phmid, g_hmid);
    cudaGetSymbolAddress((void**)&pAh, g_Ah);
    cudaGetSymbolAddress((void**)&pAl, g_Al);
    cudaGetSymbolAddress((void**)&pXh, g_Xh);
    cudaGetSymbolAddress((void**)&pXl, g_Xl);
    cudaGetSymbolAddress((void**)&pBh, g_Bh);
    cudaGetSymbolAddress((void**)&pBl, g_Bl);

    cudaFuncSetAttribute(k_mma, cudaFuncAttributeMaxDynamicSharedMemorySize, GEMM_SMEM);

    const int MT = (NN + 127) / 128;  // 157 M-tiles

    // ---- graph preprocessing (dst-CSR) + per-layer constants ----
    k_zero<<<(NN + 255) / 256, 256>>>();
    k_count<<<(EE + 255) / 256, 256>>>(dst);
    k_scan<<<1, 1024>>>();
    k_scatter<<<(EE + 255) / 256, 256>>>(src, dst);
    k_wmean<<<NL * EDIM, 256>>>(edge_enc_w);
    k_bmean<<<NL, 256>>>(edge_enc_b);
    k_cvec<<<NL * NHEADS, 256>>>(lin_edge_w, att_edge);
    k_ew3<<<(EE + 7) / 8, 256>>>(edge_attr);
    k_loopw3<<<(NN + 255) / 256, 256>>>();

    // ---- encoder: x = relu(nf @ enc_w + enc_b) -> fp16 hi/lo split only ----
    k_cvtA<<<(NN * NDIM + 255) / 256, 256>>>(node_features, pAh, pAl, NN * NDIM);
    k_cvtBT<<<(NDIM * HD + 255) / 256, 256>>>(enc_w, pBh, pBl, NDIM, HD);
    k_mma<<<dim3(HD / 128, MT), 256, GEMM_SMEM>>>(pAh, pAl, pBh, pBl,
                                                  nullptr, nullptr, pXh, pXl,
                                                  NN, HD, NDIM, enc_b, 1, nullptr, nullptr);

    // ---- 3 GAT layers ----
    for (int l = 0; l < NL; l++) {
        float* XO = (l == 2) ? out + 4 * NN : nullptr;

        // xp = x @ gat_w[l] -> fp16 xp; a_s/a_d fused into epilogue
        k_zeroAS<<<(NN * 4 + 255) / 256, 256>>>();
        k_cvtBT<<<(HD * 1024 + 255) / 256, 256>>>(gat_w + (size_t)l * 256 * 1024,
                                                  pBh, pBl, HD, 1024);
        k_mma<<<dim3(1024 / 128, MT), 256, GEMM_SMEM>>>(pXh, pXl, pBh, pBl,
                                                        nullptr, pxph, nullptr, nullptr,
                                                        NN, 1024, HD, nullptr, 0,
                                                        att_src + l * 1024, att_dst + l * 1024);

        k_gather<<<NN, 256>>>(XO, pXh, pXl, l,
                              gat_b + l * 256, ln_g + l * 256, ln_b + l * 256);
    }
    // emb in out[4*NN ..]; fp16 hi/lo split in pXh/pXl

    // ---- combined prediction heads: hmid = relu(emb @ [W1_0|W1_1|W1_2|W1_3] + b1) ----
    k_cvtHW<<<(512 * 256 + 255) / 256, 256>>>(head_w1, pBh, pBl);
    k_mma<<<dim3(512 / 128, MT), 256, GEMM_SMEM>>>(pXh, pXl, pBh, pBl,
                                                   phmid, nullptr, nullptr, nullptr,
                                                   NN, 512, HD, head_b1, 1, nullptr, nullptr);
    k_headout<<<NN, 128>>>(head_w2, head_b2, out);
}

// round 16
// speedup vs baseline: 1.1163x; 1.0348x over previous
#include <cuda_runtime.h>
#include <cuda_fp16.h>
#include <cstdint>
#include <math.h>

#define NN 20000
#define EE 200000
#define HD 256
#define NHEADS 4
#define NDIM 128
#define EDIM 64
#define NL 3

// ---------------- scratch (static device globals; no runtime allocation) ----------------
__device__ __half g_xph[(size_t)NN * NHEADS * HD];  // xp in fp16 [N,1024]
__device__ float g_as [NN * NHEADS];
__device__ float g_ad [NN * NHEADS];
__device__ float g_ew [NL * EE];
__device__ float g_loopw[NL * NN];
__device__ int   g_counts[NN];
__device__ int   g_cursor[NN];
__device__ int   g_rowptr[NN + 1];
__device__ int   g_csrc[EE];
__device__ int   g_ceid[EE];
__device__ float g_wmean[NL * EDIM];
__device__ float g_bmean[NL];
__device__ float g_cvec [NL * NHEADS];
// fp16 hi/lo split buffers (A = activations, B = weights)
__device__ __half g_Ah[(size_t)NN * HD];
__device__ __half g_Al[(size_t)NN * HD];
__device__ __half g_Xh[(size_t)NN * HD];    // activation x split (exact fp32 = hi+lo)
__device__ __half g_Xl[(size_t)NN * HD];
__device__ __half g_Bh[1024 * 256];
__device__ __half g_Bl[1024 * 256];

// ---------------- helpers ----------------
__device__ __forceinline__ float lrelu(float x) { return fmaxf(x, 0.2f * x); }

__device__ __forceinline__ void mma16816(float* c, const uint32_t* a, const uint32_t* b) {
    asm volatile(
        "mma.sync.aligned.m16n8k16.row.col.f32.f16.f16.f32 "
        "{%0,%1,%2,%3}, {%4,%5,%6,%7}, {%8,%9}, {%0,%1,%2,%3};"
        : "+f"(c[0]), "+f"(c[1]), "+f"(c[2]), "+f"(c[3])
        : "r"(a[0]), "r"(a[1]), "r"(a[2]), "r"(a[3]), "r"(b[0]), "r"(b[1]));
}
__device__ __forceinline__ void ldsm4(uint32_t addr, uint32_t* r) {
    asm volatile("ldmatrix.sync.aligned.m8n8.x4.shared.b16 {%0,%1,%2,%3}, [%4];"
                 : "=r"(r[0]), "=r"(r[1]), "=r"(r[2]), "=r"(r[3]) : "r"(addr));
}
__device__ __forceinline__ void cpa16z(uint32_t dst, const void* src, int sz) {
    asm volatile("cp.async.cg.shared.global [%0], [%1], 16, %2;"
                 :: "r"(dst), "l"(src), "r"(sz));
}
__device__ __forceinline__ float4 h4tof4(uint2 u) {
    __half2 a = *(__half2*)&u.x, b = *(__half2*)&u.y;
    float2 fa = __half22float2(a), fb = __half22float2(b);
    return make_float4(fa.x, fa.y, fb.x, fb.y);
}

// ---------------- fp16x3 GEMM (A,B both hi/lo split), double-buffered cp.async ----------------
// C = A@B; error ~2^-21 (dropped al*bl). Block 128x128, 8 warps, warp 64x32, K-chunk 32.
// Fused epilogues: attention dots (attS/attD), xp fp16 store (Cxp), hi/lo split (Chi/Clo),
// OR full prediction-head finish (w2/b2 -> outHead, CTA nb == head index).
#define KCH 32
#define AST 40                       // smem row stride fp16 (80B: conflict-free ldmatrix)
#define STG (128 * AST)
#define GEMM_SMEM (8 * STG * 2)      // 81920 bytes
__global__ __launch_bounds__(256, 2) void k_mma(
    const __half* __restrict__ Ah, const __half* __restrict__ Al,
    const __half* __restrict__ Bh, const __half* __restrict__ Bl,
    float* __restrict__ C, __half* __restrict__ Cxp,
    __half* __restrict__ Chi, __half* __restrict__ Clo,
    int M, int N, int K, const float* __restrict__ bias, int doRelu,
    const float* __restrict__ attS, const float* __restrict__ attD,
    const float* __restrict__ w2, const float* __restrict__ b2,
    float* __restrict__ outHead) {
    extern __shared__ __half sm[];
    __shared__ float sAS[128], sAD[128];
    uint32_t base = (uint32_t)__cvta_generic_to_shared(sm);

    int tid = threadIdx.x, lane = tid & 31, wid = tid >> 5;
    int nb = blockIdx.x, mb = blockIdx.y;
    int warpM = wid >> 2, warpN = wid & 3;
    int gid = lane >> 2, qid = lane & 3;
    int NC = K / KCH;

    auto offAh = [&](int s) { return base + (uint32_t)(4 * s) * STG * 2; };
    auto offAl = [&](int s) { return base + (uint32_t)(4 * s + 1) * STG * 2; };
    auto offBh = [&](int s) { return base + (uint32_t)(4 * s + 2) * STG * 2; };
    auto offBl = [&](int s) { return base + (uint32_t)(4 * s + 3) * STG * 2; };

    auto load_chunk = [&](int kc, int s) {
        int k0 = kc * KCH;
#pragma unroll
        for (int i = tid; i < 512; i += 256) {
            int row = i >> 2, c = i & 3;
            uint32_t so = (uint32_t)(row * AST + c * 8) * 2;
            int gr = mb * 128 + row;
            int sz = (gr < M) ? 16 : 0;
            int grc = (gr < M) ? gr : (M - 1);
            cpa16z(offAh(s) + so, Ah + (size_t)grc * K + k0 + c * 8, sz);
            cpa16z(offAl(s) + so, Al + (size_t)grc * K + k0 + c * 8, sz);
            int gn = nb * 128 + row;
            cpa16z(offBh(s) + so, Bh + (size_t)gn * K + k0 + c * 8, 16);
            cpa16z(offBl(s) + so, Bl + (size_t)gn * K + k0 + c * 8, 16);
        }
        asm volatile("cp.async.commit_group;");
    };

    float acc[4][4][4];
#pragma unroll
    for (int i = 0; i < 4; i++)
#pragma unroll
        for (int j = 0; j < 4; j++)
#pragma unroll
            for (int k = 0; k < 4; k++) acc[i][j][k] = 0.f;

    int aRow = (lane & 15), aCol = (lane >> 4) * 8;
    int bRow = (lane & 7) + ((lane >> 4) << 3), bCol = ((lane >> 3) & 1) * 8;

    load_chunk(0, 0);

    for (int kc = 0; kc < NC; kc++) {
        int s = kc & 1;
        if (kc + 1 < NC) {
            load_chunk(kc + 1, s ^ 1);
            asm volatile("cp.async.wait_group 1;" ::: "memory");
        } else {
            asm volatile("cp.async.wait_group 0;" ::: "memory");
        }
        __syncthreads();

#pragma unroll
        for (int ks = 0; ks < KCH; ks += 16) {
            uint32_t ah[4][4], al[4][4], bh[2][4], bl[2][4];
#pragma unroll
            for (int mt = 0; mt < 4; mt++) {
                uint32_t o = (uint32_t)((warpM * 64 + mt * 16 + aRow) * AST + ks + aCol) * 2;
                ldsm4(offAh(s) + o, ah[mt]);
                ldsm4(offAl(s) + o, al[mt]);
            }
#pragma unroll
            for (int np = 0; np < 2; np++) {
                uint32_t o = (uint32_t)((warpN * 32 + np * 16 + bRow) * AST + ks + bCol) * 2;
                ldsm4(offBh(s) + o, bh[np]);
                ldsm4(offBl(s) + o, bl[np]);
            }
#pragma unroll
            for (int mt = 0; mt < 4; mt++)
#pragma unroll
                for (int nt = 0; nt < 4; nt++) {
                    const uint32_t* bhp = &bh[nt >> 1][(nt & 1) * 2];
                    const uint32_t* blp = &bl[nt >> 1][(nt & 1) * 2];
                    mma16816(acc[mt][nt], ah[mt], bhp);
                    mma16816(acc[mt][nt], al[mt], bhp);
                    mma16816(acc[mt][nt], ah[mt], blp);
                }
        }
        __syncthreads();
    }

    // ---- fused attention dots from exact fp32 accumulators (CTA covers 1 head) ----
    if (attS) {
        if (tid < 128) { sAS[tid] = 0.f; sAD[tid] = 0.f; }
        __syncthreads();
        float avS[8], avD[8];
#pragma unroll
        for (int nt = 0; nt < 4; nt++) {
            int cn = nb * 128 + warpN * 32 + nt * 8 + qid * 2;
            avS[nt * 2] = attS[cn];
            avS[nt * 2 + 1] = attS[cn + 1];
            avD[nt * 2] = attD[cn];
            avD[nt * 2 + 1] = attD[cn + 1];
        }
#pragma unroll
        for (int mt = 0; mt < 4; mt++)
#pragma unroll
            for (int half = 0; half < 2; half++) {
                float sp = 0.f, dp = 0.f;
#pragma unroll
                for (int nt = 0; nt < 4; nt++) {
                    float a0 = acc[mt][nt][half * 2], a1 = acc[mt][nt][half * 2 + 1];
                    sp += a0 * avS[nt * 2] + a1 * avS[nt * 2 + 1];
                    dp += a0 * avD[nt * 2] + a1 * avD[nt * 2 + 1];
                }
                sp += __shfl_xor_sync(0xffffffffu, sp, 1);
                sp += __shfl_xor_sync(0xffffffffu, sp, 2);
                dp += __shfl_xor_sync(0xffffffffu, dp, 1);
                dp += __shfl_xor_sync(0xffffffffu, dp, 2);
                if (qid == 0) {
                    int rl = warpM * 64 + mt * 16 + gid + half * 8;
                    atomicAdd(&sAS[rl], sp);
                    atomicAdd(&sAD[rl], dp);
                }
            }
        __syncthreads();
        if (tid < 128) {
            int r = mb * 128 + tid;
            if (r < M) {
                int h = nb >> 1;   // 128 cols/CTA, 256 cols/head
                atomicAdd(&g_as[r * 4 + h], sAS[tid]);
                atomicAdd(&g_ad[r * 4 + h], sAD[tid]);
            }
        }
    }

    // ---- fused prediction-head finish: out[nb][r] = act( sum_col relu(acc+b1)*w2 + b2 ) ----
    if (w2) {
        if (tid < 128) sAS[tid] = 0.f;
        __syncthreads();
        float wv[8];
#pragma unroll
        for (int nt = 0; nt < 4; nt++) {
            int col = warpN * 32 + nt * 8 + qid * 2;        // col within this head's 128 dims
            wv[nt * 2] = w2[nb * 128 + col];
            wv[nt * 2 + 1] = w2[nb * 128 + col + 1];
        }
#pragma unroll
        for (int mt = 0; mt < 4; mt++)
#pragma unroll
            for (int half = 0; half < 2; half++) {
                float sp = 0.f;
#pragma unroll
                for (int nt = 0; nt < 4; nt++) {
                    int cn = nb * 128 + warpN * 32 + nt * 8 + qid * 2;
                    float v0 = fmaxf(acc[mt][nt][half * 2] + bias[cn], 0.f);
                    float v1 = fmaxf(acc[mt][nt][half * 2 + 1] + bias[cn + 1], 0.f);
                    sp += v0 * wv[nt * 2] + v1 * wv[nt * 2 + 1];
                }
                sp += __shfl_xor_sync(0xffffffffu, sp, 1);
                sp += __shfl_xor_sync(0xffffffffu, sp, 2);
                if (qid == 0) {
                    int rl = warpM * 64 + mt * 16 + gid + half * 8;
                    atomicAdd(&sAS[rl], sp);
                }
            }
        __syncthreads();
        if (tid < 128) {
            int r = mb * 128 + tid;
            if (r < M) {
                float v = sAS[tid] + b2[nb];
                if (nb == 0 || nb == 3) v = 1.f / (1.f + expf(-v));
                outHead[(size_t)nb * NN + r] = v;
            }
        }
        return;   // no other stores for the head GEMM
    }

    // ---- stores: C fp32 (optional), Cxp fp16 (optional), Chi/Clo hi-lo split (optional) ----
#pragma unroll
    for (int mt = 0; mt < 4; mt++) {
        int r0 = mb * 128 + warpM * 64 + mt * 16 + gid;
#pragma unroll
        for (int nt = 0; nt < 4; nt++) {
            int cn = nb * 128 + warpN * 32 + nt * 8 + qid * 2;
            float b0 = bias ? bias[cn] : 0.f;
            float b1 = bias ? bias[cn + 1] : 0.f;
#pragma unroll
            for (int half = 0; half < 2; half++) {
                int r = r0 + half * 8;
                if (r < M) {
                    float v0 = acc[mt][nt][half * 2 + 0] + b0;
                    float v1 = acc[mt][nt][half * 2 + 1] + b1;
                    if (doRelu) { v0 = fmaxf(v0, 0.f); v1 = fmaxf(v1, 0.f); }
                    size_t o = (size_t)r * N + cn;
                    if (C) {
                        C[o] = v0;
                        C[o + 1] = v1;
                    }
                    if (Cxp) {
                        *(__half2*)&Cxp[o] = __floats2half2_rn(v0, v1);
                    }
                    if (Chi) {
                        __half h0 = __float2half(v0);
                        __half h1 = __float2half(v1);
                        __half2 hh, ll;
                        hh.x = h0; hh.y = h1;
                        ll.x = __float2half(v0 - __half2float(h0));
                        ll.y = __float2half(v1 - __half2float(h1));
                        *(__half2*)&Chi[o] = hh;
                        *(__half2*)&Clo[o] = ll;
                    }
                }
            }
        }
    }
}

// ---------------- fp16 hi/lo conversions ----------------
__global__ void k_cvtA(const float* __restrict__ in, __half* __restrict__ hi,
                       __half* __restrict__ lo, int n) {
    int i = blockIdx.x * 256 + threadIdx.x;
    if (i < n) {
        float v = in[i];
        __half h = __float2half(v);
        hi[i] = h;
        lo[i] = __float2half(v - __half2float(h));
    }
}
// weights [K,N] fp32 -> [N,K] fp16 hi/lo (transpose; K-contiguous); optionally zero as/ad
__global__ void k_cvtBT(const float* __restrict__ in, __half* __restrict__ hi,
                        __half* __restrict__ lo, int K, int N, int zeroAS) {
    int i = blockIdx.x * 256 + threadIdx.x;
    if (zeroAS && i < NN * 4) { g_as[i] = 0.f; g_ad[i] = 0.f; }
    if (i < K * N) {
        int kk = i / N, n = i % N;
        float v = in[i];
        __half h = __float2half(v);
        size_t o = (size_t)n * K + kk;
        hi[o] = h;
        lo[o] = __float2half(v - __half2float(h));
    }
}
// head_w1 [4][256][128] -> combined B [512][256] K-contiguous fp16 split
__global__ void k_cvtHW(const float* __restrict__ in, __half* __restrict__ hi,
                        __half* __restrict__ lo) {
    int i = blockIdx.x * 256 + threadIdx.x;   // over 512*256
    if (i < 512 * 256) {
        int n = i >> 8, kk = i & 255;
        float v = in[(n >> 7) * 32768 + kk * 128 + (n & 127)];
        __half h = __float2half(v);
        hi[i] = h;
        lo[i] = __float2half(v - __half2float(h));
    }
}

// ---------------- preprocessing ----------------
__global__ void k_zero() {
    int i = blockIdx.x * 256 + threadIdx.x;
    if (i < NN) { g_counts[i] = 0; g_cursor[i] = 0; }
}
__global__ void k_count(const int* __restrict__ dst) {
    int e = blockIdx.x * 256 + threadIdx.x;
    if (e < EE) atomicAdd(&g_counts[dst[e]], 1);
}
__global__ void k_scan() {
    __shared__ int sh[1024];
    int tid = threadIdx.x;
    int carry = 0;
    for (int base = 0; base < NN; base += 1024) {
        int i = base + tid;
        int v = (i < NN) ? g_counts[i] : 0;
        sh[tid] = v;
        __syncthreads();
        for (int off = 1; off < 1024; off <<= 1) {
            int t = (tid >= off) ? sh[tid - off] : 0;
            __syncthreads();
            sh[tid] += t;
            __syncthreads();
        }
        if (i < NN) g_rowptr[i + 1] = carry + sh[tid];
        carry += sh[1023];
        __syncthreads();
    }
    if (tid == 0) g_rowptr[0] = 0;
}
__global__ void k_scatter(const int* __restrict__ src, const int* __restrict__ dst) {
    int e = blockIdx.x * 256 + threadIdx.x;
    if (e < EE) {
        int d = dst[e];
        int pos = g_rowptr[d] + atomicAdd(&g_cursor[d], 1);
        g_csrc[pos] = src[e];
        g_ceid[pos] = e;
    }
}
__global__ void k_wmean(const float* __restrict__ W) {
    __shared__ float red[256];
    int ld = blockIdx.x;
    red[threadIdx.x] = W[(size_t)ld * 256 + threadIdx.x];
    __syncthreads();
    for (int s = 128; s; s >>= 1) {
        if (threadIdx.x < s) red[threadIdx.x] += red[threadIdx.x + s];
        __syncthreads();
    }
    if (threadIdx.x == 0) g_wmean[ld] = red[0] * (1.f / 256.f);
}
__global__ void k_bmean(const float* __restrict__ b) {
    __shared__ float red[256];
    int l = blockIdx.x;
    red[threadIdx.x] = b[l * 256 + threadIdx.x];
    __syncthreads();
    for (int s = 128; s; s >>= 1) {
        if (threadIdx.x < s) red[threadIdx.x] += red[threadIdx.x + s];
        __syncthreads();
    }
    if (threadIdx.x == 0) g_bmean[l] = red[0] * (1.f / 256.f);
}
__global__ void k_cvec(const float* __restrict__ lew, const float* __restrict__ ae) {
    __shared__ float red[256];
    int lh = blockIdx.x;
    size_t off = (size_t)lh * 256 + threadIdx.x;
    red[threadIdx.x] = lew[off] * ae[off];
    __syncthreads();
    for (int s = 128; s; s >>= 1) {
        if (threadIdx.x < s) red[threadIdx.x] += red[threadIdx.x + s];
        __syncthreads();
    }
    if (threadIdx.x == 0) g_cvec[lh] = red[0];
}
__global__ void k_ew3(const float* __restrict__ ea) {
    int warp = threadIdx.x >> 5, lane = threadIdx.x & 31;
    int e = blockIdx.x * 8 + warp;
    if (e >= EE) return;
    const float* row = ea + (size_t)e * EDIM;
    float v0 = row[lane], v1 = row[lane + 32];
    float s0 = v0 * g_wmean[lane] + v1 * g_wmean[lane + 32];
    float s1 = v0 * g_wmean[64 + lane] + v1 * g_wmean[64 + lane + 32];
    float s2 = v0 * g_wmean[128 + lane] + v1 * g_wmean[128 + lane + 32];
    for (int o = 16; o; o >>= 1) {
        s0 += __shfl_down_sync(0xffffffff, s0, o);
        s1 += __shfl_down_sync(0xffffffff, s1, o);
        s2 += __shfl_down_sync(0xffffffff, s2, o);
    }
    if (lane == 0) {
        g_ew[e] = s0 + g_bmean[0];
        g_ew[EE + e] = s1 + g_bmean[1];
        g_ew[2 * EE + e] = s2 + g_bmean[2];
    }
}
__global__ void k_loopw3() {
    int n = blockIdx.x * 256 + threadIdx.x;
    if (n < NN) {
        int b = g_rowptr[n], e = g_rowptr[n + 1];
        float s0 = 0.f, s1 = 0.f, s2 = 0.f;
        for (int p = b; p < e; p++) {
            int id = g_ceid[p];
            s0 += g_ew[id];
            s1 += g_ew[EE + id];
            s2 += g_ew[2 * EE + id];
        }
        float inv = 1.f / fmaxf((float)(e - b), 1.f);
        g_loopw[n] = s0 * inv;
        g_loopw[NN + n] = s1 * inv;
        g_loopw[2 * NN + n] = s2 * inv;
    }
}

// ---------------- fused GAT: online softmax + fp16 gather + LN + residual + split out ----------------
#define GCH 128
__global__ __launch_bounds__(256) void k_gather(float* __restrict__ outF,
                                                __half* __restrict__ xh,
                                                __half* __restrict__ xl,
                                                int l,
                                                const float* __restrict__ gat_b,
                                                const float* __restrict__ ln_g,
                                                const float* __restrict__ ln_b) {
    int n = blockIdx.x, tid = threadIdx.x;
    int lane = tid & 31, wid = tid >> 5;
    int head = tid >> 6, f4 = tid & 63;
    __shared__ int ssrc[GCH];
    __shared__ float slog[GCH][4];
    __shared__ float wt[GCH][4];
    __shared__ float sm4[4], ss4[4], sf4[4];
    __shared__ float sred[1024];
    __shared__ float sw[8];
    __shared__ float sMu, sVar;

    int beg = g_rowptr[n];
    int deg = g_rowptr[n + 1] - beg;

    float4 adv = *(const float4*)&g_ad[n * 4];
    float4 cv = *(const float4*)&g_cvec[l * 4];
    float lw = g_loopw[l * NN + n];
    if (tid < 4) {
        float sl = lrelu(g_as[n * 4 + tid] + g_ad[n * 4 + tid] + lw * g_cvec[l * 4 + tid]);
        sm4[tid] = sl;
        ss4[tid] = 1.f;
    }
    __syncthreads();

    const uint2* xp2 = (const uint2*)g_xph;   // 4 halfs per uint2
    size_t hb = (size_t)head * 64 + f4;
    float4 acc = h4tof4(xp2[(size_t)n * 256 + hb]);   // self, weight 1 at current max

    for (int ch = 0; ch < deg; ch += GCH) {
        int cnt = min(GCH, deg - ch);
        if (tid < cnt) {
            int p = beg + ch + tid;
            int s0 = g_csrc[p];
            float w = g_ew[l * EE + g_ceid[p]];
            ssrc[tid] = s0;
            float4 as4 = *(const float4*)&g_as[s0 * 4];
            slog[tid][0] = lrelu(as4.x + adv.x + w * cv.x);
            slog[tid][1] = lrelu(as4.y + adv.y + w * cv.y);
            slog[tid][2] = lrelu(as4.z + adv.z + w * cv.z);
            slog[tid][3] = lrelu(as4.w + adv.w + w * cv.w);
        }
        __syncthreads();
        if (wid < 4) {
            int h = wid;
            float cm = -1e30f;
            for (int j = lane; j < cnt; j += 32) cm = fmaxf(cm, slog[j][h]);
            for (int o = 16; o; o >>= 1) cm = fmaxf(cm, __shfl_xor_sync(0xffffffff, cm, o));
            float mold = sm4[h];
            float mnew = fmaxf(mold, cm);
            float fac = expf(mold - mnew);
            float cs = 0.f;
            for (int j = lane; j < cnt; j += 32) {
                float p = expf(slog[j][h] - mnew);
                wt[j][h] = p;
                cs += p;
            }
            for (int o = 16; o; o >>= 1) cs += __shfl_xor_sync(0xffffffff, cs, o);
            if (lane == 0) {
                ss4[h] = ss4[h] * fac + cs;
                sm4[h] = mnew;
                sf4[h] = fac;
            }
        }
        __syncthreads();
        float f = sf4[head];
        acc.x *= f; acc.y *= f; acc.z *= f; acc.w *= f;
        int j = 0;
        for (; j + 4 <= cnt; j += 4) {
            float a0 = wt[j][head], a1 = wt[j + 1][head];
            float a2 = wt[j + 2][head], a3 = wt[j + 3][head];
            float4 v0 = h4tof4(xp2[(size_t)ssrc[j] * 256 + hb]);
            float4 v1 = h4tof4(xp2[(size_t)ssrc[j + 1] * 256 + hb]);
            float4 v2 = h4tof4(xp2[(size_t)ssrc[j + 2] * 256 + hb]);
            float4 v3 = h4tof4(xp2[(size_t)ssrc[j + 3] * 256 + hb]);
            acc.x += a0 * v0.x + a1 * v1.x + a2 * v2.x + a3 * v3.x;
            acc.y += a0 * v0.y + a1 * v1.y + a2 * v2.y + a3 * v3.y;
            acc.z += a0 * v0.z + a1 * v1.z + a2 * v2.z + a3 * v3.z;
            acc.w += a0 * v0.w + a1 * v1.w + a2 * v2.w + a3 * v3.w;
        }
        for (; j < cnt; j++) {
            float a = wt[j][head];
            float4 v = h4tof4(xp2[(size_t)ssrc[j] * 256 + hb]);
            acc.x += a * v.x;
            acc.y += a * v.y;
            acc.z += a * v.z;
            acc.w += a * v.w;
        }
        __syncthreads();   // before smem reuse next chunk
    }

    float inv = 0.25f / ss4[head];
    acc.x *= inv; acc.y *= inv; acc.z *= inv; acc.w *= inv;
    *(float4*)&sred[head * 256 + f4 * 4] = acc;
    __syncthreads();

    float h = sred[tid] + sred[256 + tid] + sred[512 + tid] + sred[768 + tid] + gat_b[tid];

    float v = h;
    for (int o = 16; o; o >>= 1) v += __shfl_xor_sync(0xffffffff, v, o);
    if (lane == 0) sw[wid] = v;
    __syncthreads();
    if (tid == 0) {
        float t = sw[0] + sw[1] + sw[2] + sw[3] + sw[4] + sw[5] + sw[6] + sw[7];
        sMu = t * (1.f / 256.f);
    }
    __syncthreads();
    float df = h - sMu;
    v = df * df;
    for (int o = 16; o; o >>= 1) v += __shfl_xor_sync(0xffffffff, v, o);
    __syncthreads();
    if (lane == 0) sw[wid] = v;
    __syncthreads();
    if (tid == 0) {
        float t = sw[0] + sw[1] + sw[2] + sw[3] + sw[4] + sw[5] + sw[6] + sw[7];
        sVar = t * (1.f / 256.f);
    }
    __syncthreads();
    float y = ln_g[tid] * df * rsqrtf(sVar + 1e-5f) + ln_b[tid];
    size_t idx = (size_t)n * 256 + tid;
    // residual from exact fp16 hi/lo reconstruction (error ~2^-22)
    float xr = __half2float(xh[idx]) + __half2float(xl[idx]);
    float o = fmaxf(xr + y, 0.f);
    if (outF) outF[idx] = o;
    __half hh = __float2half(o);
    xh[idx] = hh;
    xl[idx] = __float2half(o - __half2float(hh));
}

// ---------------- launch ----------------
extern "C" void kernel_launch(void* const* d_in, const int* in_sizes, int n_in,
                              void* d_out, int out_size) {
    const float* node_features = (const float*)d_in[0];
    const float* edge_attr     = (const float*)d_in[1];
    const float* enc_w         = (const float*)d_in[2];
    const float* enc_b         = (const float*)d_in[3];
    const float* edge_enc_w    = (const float*)d_in[4];
    const float* edge_enc_b    = (const float*)d_in[5];
    const float* gat_w         = (const float*)d_in[6];
    const float* att_src       = (const float*)d_in[7];
    const float* att_dst       = (const float*)d_in[8];
    const float* att_edge      = (const float*)d_in[9];
    const float* lin_edge_w    = (const float*)d_in[10];
    const float* gat_b         = (const float*)d_in[11];
    const float* ln_g          = (const float*)d_in[12];
    const float* ln_b          = (const float*)d_in[13];
    const float* head_w1       = (const float*)d_in[14];
    const float* head_b1       = (const float*)d_in[15];
    const float* head_w2       = (const float*)d_in[16];
    const float* head_b2       = (const float*)d_in[17];
    const int*   src           = (const int*)d_in[18];
    const int*   dst           = src + EE;
    float* out = (float*)d_out;

    __half *pxph, *pAh, *pAl, *pXh, *pXl, *pBh, *pBl;
    cudaGetSymbolAddress((void**)&pxph, g_xph);
    cudaGetSymbolAddress((void**)&pAh, g_Ah);
    cudaGetSymbolAddress((void**)&pAl, g_Al);
    cudaGetSymbolAddress((void**)&pXh, g_Xh);
    cudaGetSymbolAddress((void**)&pXl, g_Xl);
    cudaGetSymbolAddress((void**)&pBh, g_Bh);
    cudaGetSymbolAddress((void**)&pBl, g_Bl);

    cudaFuncSetAttribute(k_mma, cudaFuncAttributeMaxDynamicSharedMemorySize, GEMM_SMEM);

    const int MT = (NN + 127) / 128;  // 157 M-tiles

    // ---- graph preprocessing (dst-CSR) + per-layer constants ----
    k_zero<<<(NN + 255) / 256, 256>>>();
    k_count<<<(EE + 255) / 256, 256>>>(dst);
    k_scan<<<1, 1024>>>();
    k_scatter<<<(EE + 255) / 256, 256>>>(src, dst);
    k_wmean<<<NL * EDIM, 256>>>(edge_enc_w);
    k_bmean<<<NL, 256>>>(edge_enc_b);
    k_cvec<<<NL * NHEADS, 256>>>(lin_edge_w, att_edge);
    k_ew3<<<(EE + 7) / 8, 256>>>(edge_attr);
    k_loopw3<<<(NN + 255) / 256, 256>>>();

    // ---- encoder: x = relu(nf @ enc_w + enc_b) -> fp16 hi/lo split only ----
    k_cvtA<<<(NN * NDIM + 255) / 256, 256>>>(node_features, pAh, pAl, NN * NDIM);
    k_cvtBT<<<(NDIM * HD + 255) / 256, 256>>>(enc_w, pBh, pBl, NDIM, HD, 0);
    k_mma<<<dim3(HD / 128, MT), 256, GEMM_SMEM>>>(pAh, pAl, pBh, pBl,
                                                  nullptr, nullptr, pXh, pXl,
                                                  NN, HD, NDIM, enc_b, 1, nullptr, nullptr,
                                                  nullptr, nullptr, nullptr);

    // ---- 3 GAT layers ----
    for (int l = 0; l < NL; l++) {
        float* XO = (l == 2) ? out + 4 * NN : nullptr;

        // weight convert (+ zero as/ad); xp = x @ gat_w[l] -> fp16 xp; a_s/a_d fused
        k_cvtBT<<<(HD * 1024 + 255) / 256, 256>>>(gat_w + (size_t)l * 256 * 1024,
                                                  pBh, pBl, HD, 1024, 1);
        k_mma<<<dim3(1024 / 128, MT), 256, GEMM_SMEM>>>(pXh, pXl, pBh, pBl,
                                                        nullptr, pxph, nullptr, nullptr,
                                                        NN, 1024, HD, nullptr, 0,
                                                        att_src + l * 1024, att_dst + l * 1024,
                                                        nullptr, nullptr, nullptr);

        k_gather<<<NN, 256>>>(XO, pXh, pXl, l,
                              gat_b + l * 256, ln_g + l * 256, ln_b + l * 256);
    }
    // emb in out[4*NN ..]; fp16 hi/lo split in pXh/pXl

    // ---- prediction heads fully fused into one GEMM (N=512; CTA nb == head) ----
    k_cvtHW<<<(512 * 256 + 255) / 256, 256>>>(head_w1, pBh, pBl);
    k_mma<<<dim3(512 / 128, MT), 256, GEMM_SMEM>>>(pXh, pXl, pBh, pBl,
                                                   nullptr, nullptr, nullptr, nullptr,
                                                   NN, 512, HD, head_b1, 0, nullptr, nullptr,
                                                   head_w2, head_b2, out);
}

// round 17
// speedup vs baseline: 1.1776x; 1.0549x over previous
#include <cuda_runtime.h>
#include <cuda_fp16.h>
#include <cstdint>
#include <math.h>

#define NN 20000
#define EE 200000
#define HD 256
#define NHEADS 4
#define NDIM 128
#define EDIM 64
#define NL 3

// ---------------- scratch (static device globals; no runtime allocation) ----------------
__device__ __half g_xph[(size_t)NN * NHEADS * HD];  // xp in fp16 [N,1024]
__device__ float g_as [NN * NHEADS];
__device__ float g_ad [NN * NHEADS];
__device__ float g_ew [NL * EE];
__device__ float g_loopw[NL * NN];
__device__ int   g_counts[NN];
__device__ int   g_cursor[NN];
__device__ int   g_rowptr[NN + 1];
__device__ int   g_csrc[EE];
__device__ int   g_ceid[EE];
__device__ float g_wmean[NL * EDIM];
__device__ float g_bmean[NL];
__device__ float g_cvec [NL * NHEADS];
// fp16 hi/lo split buffers (A = activations, B/B2 = double-buffered weights)
__device__ __half g_Ah[(size_t)NN * HD];
__device__ __half g_Al[(size_t)NN * HD];
__device__ __half g_Xh[(size_t)NN * HD];    // activation x split (exact fp32 = hi+lo)
__device__ __half g_Xl[(size_t)NN * HD];
__device__ __half g_Bh[1024 * 256];
__device__ __half g_Bl[1024 * 256];
__device__ __half g_B2h[1024 * 256];
__device__ __half g_B2l[1024 * 256];

// ---------------- helpers ----------------
__device__ __forceinline__ float lrelu(float x) { return fmaxf(x, 0.2f * x); }

__device__ __forceinline__ void mma16816(float* c, const uint32_t* a, const uint32_t* b) {
    asm volatile(
        "mma.sync.aligned.m16n8k16.row.col.f32.f16.f16.f32 "
        "{%0,%1,%2,%3}, {%4,%5,%6,%7}, {%8,%9}, {%0,%1,%2,%3};"
        : "+f"(c[0]), "+f"(c[1]), "+f"(c[2]), "+f"(c[3])
        : "r"(a[0]), "r"(a[1]), "r"(a[2]), "r"(a[3]), "r"(b[0]), "r"(b[1]));
}
__device__ __forceinline__ void ldsm4(uint32_t addr, uint32_t* r) {
    asm volatile("ldmatrix.sync.aligned.m8n8.x4.shared.b16 {%0,%1,%2,%3}, [%4];"
                 : "=r"(r[0]), "=r"(r[1]), "=r"(r[2]), "=r"(r[3]) : "r"(addr));
}
__device__ __forceinline__ void cpa16z(uint32_t dst, const void* src, int sz) {
    asm volatile("cp.async.cg.shared.global [%0], [%1], 16, %2;"
                 :: "r"(dst), "l"(src), "r"(sz));
}
__device__ __forceinline__ float4 h4tof4(uint2 u) {
    __half2 a = *(__half2*)&u.x, b = *(__half2*)&u.y;
    float2 fa = __half22float2(a), fb = __half22float2(b);
    return make_float4(fa.x, fa.y, fb.x, fb.y);
}

// ---------------- fp16x3 GEMM (A,B both hi/lo split), double-buffered cp.async ----------------
// C = A@B; error ~2^-21 (dropped al*bl). Block 128x128, 8 warps, warp 64x32, K-chunk 32.
// Fused epilogues: attention dots (attS/attD), xp fp16 store (Cxp), hi/lo split (Chi/Clo),
// OR full prediction-head finish (w2/b2 -> outHead, CTA nb == head index).
#define KCH 32
#define AST 40                       // smem row stride fp16 (80B: conflict-free ldmatrix)
#define STG (128 * AST)
#define GEMM_SMEM (8 * STG * 2)      // 81920 bytes
__global__ __launch_bounds__(256, 2) void k_mma(
    const __half* __restrict__ Ah, const __half* __restrict__ Al,
    const __half* __restrict__ Bh, const __half* __restrict__ Bl,
    float* __restrict__ C, __half* __restrict__ Cxp,
    __half* __restrict__ Chi, __half* __restrict__ Clo,
    int M, int N, int K, const float* __restrict__ bias, int doRelu,
    const float* __restrict__ attS, const float* __restrict__ attD,
    const float* __restrict__ w2, const float* __restrict__ b2,
    float* __restrict__ outHead) {
    extern __shared__ __half sm[];
    __shared__ float sAS[128], sAD[128];
    uint32_t base = (uint32_t)__cvta_generic_to_shared(sm);

    int tid = threadIdx.x, lane = tid & 31, wid = tid >> 5;
    int nb = blockIdx.x, mb = blockIdx.y;
    int warpM = wid >> 2, warpN = wid & 3;
    int gid = lane >> 2, qid = lane & 3;
    int NC = K / KCH;

    auto offAh = [&](int s) { return base + (uint32_t)(4 * s) * STG * 2; };
    auto offAl = [&](int s) { return base + (uint32_t)(4 * s + 1) * STG * 2; };
    auto offBh = [&](int s) { return base + (uint32_t)(4 * s + 2) * STG * 2; };
    auto offBl = [&](int s) { return base + (uint32_t)(4 * s + 3) * STG * 2; };

    auto load_chunk = [&](int kc, int s) {
        int k0 = kc * KCH;
#pragma unroll
        for (int i = tid; i < 512; i += 256) {
            int row = i >> 2, c = i & 3;
            uint32_t so = (uint32_t)(row * AST + c * 8) * 2;
            int gr = mb * 128 + row;
            int sz = (gr < M) ? 16 : 0;
            int grc = (gr < M) ? gr : (M - 1);
            cpa16z(offAh(s) + so, Ah + (size_t)grc * K + k0 + c * 8, sz);
            cpa16z(offAl(s) + so, Al + (size_t)grc * K + k0 + c * 8, sz);
            int gn = nb * 128 + row;
            cpa16z(offBh(s) + so, Bh + (size_t)gn * K + k0 + c * 8, 16);
            cpa16z(offBl(s) + so, Bl + (size_t)gn * K + k0 + c * 8, 16);
        }
        asm volatile("cp.async.commit_group;");
    };

    float acc[4][4][4];
#pragma unroll
    for (int i = 0; i < 4; i++)
#pragma unroll
        for (int j = 0; j < 4; j++)
#pragma unroll
            for (int k = 0; k < 4; k++) acc[i][j][k] = 0.f;

    int aRow = (lane & 15), aCol = (lane >> 4) * 8;
    int bRow = (lane & 7) + ((lane >> 4) << 3), bCol = ((lane >> 3) & 1) * 8;

    load_chunk(0, 0);

    for (int kc = 0; kc < NC; kc++) {
        int s = kc & 1;
        if (kc + 1 < NC) {
            load_chunk(kc + 1, s ^ 1);
            asm volatile("cp.async.wait_group 1;" ::: "memory");
        } else {
            asm volatile("cp.async.wait_group 0;" ::: "memory");
        }
        __syncthreads();

#pragma unroll
        for (int ks = 0; ks < KCH; ks += 16) {
            uint32_t ah[4][4], al[4][4], bh[2][4], bl[2][4];
#pragma unroll
            for (int mt = 0; mt < 4; mt++) {
                uint32_t o = (uint32_t)((warpM * 64 + mt * 16 + aRow) * AST + ks + aCol) * 2;
                ldsm4(offAh(s) + o, ah[mt]);
                ldsm4(offAl(s) + o, al[mt]);
            }
#pragma unroll
            for (int np = 0; np < 2; np++) {
                uint32_t o = (uint32_t)((warpN * 32 + np * 16 + bRow) * AST + ks + bCol) * 2;
                ldsm4(offBh(s) + o, bh[np]);
                ldsm4(offBl(s) + o, bl[np]);
            }
#pragma unroll
            for (int mt = 0; mt < 4; mt++)
#pragma unroll
                for (int nt = 0; nt < 4; nt++) {
                    const uint32_t* bhp = &bh[nt >> 1][(nt & 1) * 2];
                    const uint32_t* blp = &bl[nt >> 1][(nt & 1) * 2];
                    mma16816(acc[mt][nt], ah[mt], bhp);
                    mma16816(acc[mt][nt], al[mt], bhp);
                    mma16816(acc[mt][nt], ah[mt], blp);
                }
        }
        __syncthreads();
    }

    // ---- fused attention dots from exact fp32 accumulators (CTA covers 1 head) ----
    if (attS) {
        if (tid < 128) { sAS[tid] = 0.f; sAD[tid] = 0.f; }
        __syncthreads();
        float avS[8], avD[8];
#pragma unroll
        for (int nt = 0; nt < 4; nt++) {
            int cn = nb * 128 + warpN * 32 + nt * 8 + qid * 2;
            avS[nt * 2] = attS[cn];
            avS[nt * 2 + 1] = attS[cn + 1];
            avD[nt * 2] = attD[cn];
            avD[nt * 2 + 1] = attD[cn + 1];
        }
#pragma unroll
        for (int mt = 0; mt < 4; mt++)
#pragma unroll
            for (int half = 0; half < 2; half++) {
                float sp = 0.f, dp = 0.f;
#pragma unroll
                for (int nt = 0; nt < 4; nt++) {
                    float a0 = acc[mt][nt][half * 2], a1 = acc[mt][nt][half * 2 + 1];
                    sp += a0 * avS[nt * 2] + a1 * avS[nt * 2 + 1];
                    dp += a0 * avD[nt * 2] + a1 * avD[nt * 2 + 1];
                }
                sp += __shfl_xor_sync(0xffffffffu, sp, 1);
                sp += __shfl_xor_sync(0xffffffffu, sp, 2);
                dp += __shfl_xor_sync(0xffffffffu, dp, 1);
                dp += __shfl_xor_sync(0xffffffffu, dp, 2);
                if (qid == 0) {
                    int rl = warpM * 64 + mt * 16 + gid + half * 8;
                    atomicAdd(&sAS[rl], sp);
                    atomicAdd(&sAD[rl], dp);
                }
            }
        __syncthreads();
        if (tid < 128) {
            int r = mb * 128 + tid;
            if (r < M) {
                int h = nb >> 1;   // 128 cols/CTA, 256 cols/head
                atomicAdd(&g_as[r * 4 + h], sAS[tid]);
                atomicAdd(&g_ad[r * 4 + h], sAD[tid]);
            }
        }
    }

    // ---- fused prediction-head finish: out[nb][r] = act( sum_col relu(acc+b1)*w2 + b2 ) ----
    if (w2) {
        if (tid < 128) sAS[tid] = 0.f;
        __syncthreads();
        float wv[8];
#pragma unroll
        for (int nt = 0; nt < 4; nt++) {
            int col = warpN * 32 + nt * 8 + qid * 2;        // col within this head's 128 dims
            wv[nt * 2] = w2[nb * 128 + col];
            wv[nt * 2 + 1] = w2[nb * 128 + col + 1];
        }
#pragma unroll
        for (int mt = 0; mt < 4; mt++)
#pragma unroll
            for (int half = 0; half < 2; half++) {
                float sp = 0.f;
#pragma unroll
                for (int nt = 0; nt < 4; nt++) {
                    int cn = nb * 128 + warpN * 32 + nt * 8 + qid * 2;
                    float v0 = fmaxf(acc[mt][nt][half * 2] + bias[cn], 0.f);
                    float v1 = fmaxf(acc[mt][nt][half * 2 + 1] + bias[cn + 1], 0.f);
                    sp += v0 * wv[nt * 2] + v1 * wv[nt * 2 + 1];
                }
                sp += __shfl_xor_sync(0xffffffffu, sp, 1);
                sp += __shfl_xor_sync(0xffffffffu, sp, 2);
                if (qid == 0) {
                    int rl = warpM * 64 + mt * 16 + gid + half * 8;
                    atomicAdd(&sAS[rl], sp);
                }
            }
        __syncthreads();
        if (tid < 128) {
            int r = mb * 128 + tid;
            if (r < M) {
                float v = sAS[tid] + b2[nb];
                if (nb == 0 || nb == 3) v = 1.f / (1.f + expf(-v));
                outHead[(size_t)nb * NN + r] = v;
            }
        }
        return;   // no other stores for the head GEMM
    }

    // ---- stores: C fp32 (optional), Cxp fp16 (optional), Chi/Clo hi-lo split (optional) ----
#pragma unroll
    for (int mt = 0; mt < 4; mt++) {
        int r0 = mb * 128 + warpM * 64 + mt * 16 + gid;
#pragma unroll
        for (int nt = 0; nt < 4; nt++) {
            int cn = nb * 128 + warpN * 32 + nt * 8 + qid * 2;
            float b0 = bias ? bias[cn] : 0.f;
            float b1 = bias ? bias[cn + 1] : 0.f;
#pragma unroll
            for (int half = 0; half < 2; half++) {
                int r = r0 + half * 8;
                if (r < M) {
                    float v0 = acc[mt][nt][half * 2 + 0] + b0;
                    float v1 = acc[mt][nt][half * 2 + 1] + b1;
                    if (doRelu) { v0 = fmaxf(v0, 0.f); v1 = fmaxf(v1, 0.f); }
                    size_t o = (size_t)r * N + cn;
                    if (C) {
                        C[o] = v0;
                        C[o + 1] = v1;
                    }
                    if (Cxp) {
                        *(__half2*)&Cxp[o] = __floats2half2_rn(v0, v1);
                    }
                    if (Chi) {
                        __half h0 = __float2half(v0);
                        __half h1 = __float2half(v1);
                        __half2 hh, ll;
                        hh.x = h0; hh.y = h1;
                        ll.x = __float2half(v0 - __half2float(h0));
                        ll.y = __float2half(v1 - __half2float(h1));
                        *(__half2*)&Chi[o] = hh;
                        *(__half2*)&Clo[o] = ll;
                    }
                }
            }
        }
    }
}

// ---------------- fp16 hi/lo conversions ----------------
__global__ void k_cvtA(const float* __restrict__ in, __half* __restrict__ hi,
                       __half* __restrict__ lo, int n) {
    int i = blockIdx.x * 256 + threadIdx.x;
    if (i < n) {
        float v = in[i];
        __half h = __float2half(v);
        hi[i] = h;
        lo[i] = __float2half(v - __half2float(h));
    }
}
// weights [K,N] fp32 -> [N,K] fp16 hi/lo (transpose; K-contiguous)
__global__ void k_cvtBT(const float* __restrict__ in, __half* __restrict__ hi,
                        __half* __restrict__ lo, int K, int N) {
    int i = blockIdx.x * 256 + threadIdx.x;
    if (i < K * N) {
        int kk = i / N, n = i % N;
        float v = in[i];
        __half h = __float2half(v);
        size_t o = (size_t)n * K + kk;
        hi[o] = h;
        lo[o] = __float2half(v - __half2float(h));
    }
}
// head_w1 [4][256][128] -> combined B [512][256] K-contiguous fp16 split
__global__ void k_cvtHW(const float* __restrict__ in, __half* __restrict__ hi,
                        __half* __restrict__ lo) {
    int i = blockIdx.x * 256 + threadIdx.x;   // over 512*256
    if (i < 512 * 256) {
        int n = i >> 8, kk = i & 255;
        float v = in[(n >> 7) * 32768 + kk * 128 + (n & 127)];
        __half h = __float2half(v);
        hi[i] = h;
        lo[i] = __float2half(v - __half2float(h));
    }
}
__global__ void k_zeroAS() {
    int i = blockIdx.x * 256 + threadIdx.x;
    if (i < NN * 4) { g_as[i] = 0.f; g_ad[i] = 0.f; }
}

// ---------------- preprocessing ----------------
__global__ void k_zero() {
    int i = blockIdx.x * 256 + threadIdx.x;
    if (i < NN) { g_counts[i] = 0; g_cursor[i] = 0; }
}
__global__ void k_count(const int* __restrict__ dst) {
    int e = blockIdx.x * 256 + threadIdx.x;
    if (e < EE) atomicAdd(&g_counts[dst[e]], 1);
}
__global__ void k_scan() {
    __shared__ int sh[1024];
    int tid = threadIdx.x;
    int carry = 0;
    for (int base = 0; base < NN; base += 1024) {
        int i = base + tid;
        int v = (i < NN) ? g_counts[i] : 0;
        sh[tid] = v;
        __syncthreads();
        for (int off = 1; off < 1024; off <<= 1) {
            int t = (tid >= off) ? sh[tid - off] : 0;
            __syncthreads();
            sh[tid] += t;
            __syncthreads();
        }
        if (i < NN) g_rowptr[i + 1] = carry + sh[tid];
        carry += sh[1023];
        __syncthreads();
    }
    if (tid == 0) g_rowptr[0] = 0;
}
__global__ void k_scatter(const int* __restrict__ src, const int* __restrict__ dst) {
    int e = blockIdx.x * 256 + threadIdx.x;
    if (e < EE) {
        int d = dst[e];
        int pos = g_rowptr[d] + atomicAdd(&g_cursor[d], 1);
        g_csrc[pos] = src[e];
        g_ceid[pos] = e;
    }
}
__global__ void k_wmean(const float* __restrict__ W) {
    __shared__ float red[256];
    int ld = blockIdx.x;
    red[threadIdx.x] = W[(size_t)ld * 256 + threadIdx.x];
    __syncthreads();
    for (int s = 128; s; s >>= 1) {
        if (threadIdx.x < s) red[threadIdx.x] += red[threadIdx.x + s];
        __syncthreads();
    }
    if (threadIdx.x == 0) g_wmean[ld] = red[0] * (1.f / 256.f);
}
__global__ void k_bmean(const float* __restrict__ b) {
    __shared__ float red[256];
    int l = blockIdx.x;
    red[threadIdx.x] = b[l * 256 + threadIdx.x];
    __syncthreads();
    for (int s = 128; s; s >>= 1) {
        if (threadIdx.x < s) red[threadIdx.x] += red[threadIdx.x + s];
        __syncthreads();
    }
    if (threadIdx.x == 0) g_bmean[l] = red[0] * (1.f / 256.f);
}
__global__ void k_cvec(const float* __restrict__ lew, const float* __restrict__ ae) {
    __shared__ float red[256];
    int lh = blockIdx.x;
    size_t off = (size_t)lh * 256 + threadIdx.x;
    red[threadIdx.x] = lew[off] * ae[off];
    __syncthreads();
    for (int s = 128; s; s >>= 1) {
        if (threadIdx.x < s) red[threadIdx.x] += red[threadIdx.x + s];
        __syncthreads();
    }
    if (threadIdx.x == 0) g_cvec[lh] = red[0];
}
__global__ void k_ew3(const float* __restrict__ ea) {
    int warp = threadIdx.x >> 5, lane = threadIdx.x & 31;
    int e = blockIdx.x * 8 + warp;
    if (e >= EE) return;
    const float* row = ea + (size_t)e * EDIM;
    float v0 = row[lane], v1 = row[lane + 32];
    float s0 = v0 * g_wmean[lane] + v1 * g_wmean[lane + 32];
    float s1 = v0 * g_wmean[64 + lane] + v1 * g_wmean[64 + lane + 32];
    float s2 = v0 * g_wmean[128 + lane] + v1 * g_wmean[128 + lane + 32];
    for (int o = 16; o; o >>= 1) {
        s0 += __shfl_down_sync(0xffffffff, s0, o);
        s1 += __shfl_down_sync(0xffffffff, s1, o);
        s2 += __shfl_down_sync(0xffffffff, s2, o);
    }
    if (lane == 0) {
        g_ew[e] = s0 + g_bmean[0];
        g_ew[EE + e] = s1 + g_bmean[1];
        g_ew[2 * EE + e] = s2 + g_bmean[2];
    }
}
__global__ void k_loopw3() {
    int n = blockIdx.x * 256 + threadIdx.x;
    if (n < NN) {
        int b = g_rowptr[n], e = g_rowptr[n + 1];
        float s0 = 0.f, s1 = 0.f, s2 = 0.f;
        for (int p = b; p < e; p++) {
            int id = g_ceid[p];
            s0 += g_ew[id];
            s1 += g_ew[EE + id];
            s2 += g_ew[2 * EE + id];
        }
        float inv = 1.f / fmaxf((float)(e - b), 1.f);
        g_loopw[n] = s0 * inv;
        g_loopw[NN + n] = s1 * inv;
        g_loopw[2 * NN + n] = s2 * inv;
    }
}

// ---------------- fused GAT: online softmax + fp16 gather + LN + residual + split out ----------------
#define GCH 128
__global__ __launch_bounds__(256) void k_gather(float* __restrict__ outF,
                                                __half* __restrict__ xh,
                                                __half* __restrict__ xl,
                                                int l,
                                                const float* __restrict__ gat_b,
                                                const float* __restrict__ ln_g,
                                                const float* __restrict__ ln_b) {
    int n = blockIdx.x, tid = threadIdx.x;
    int lane = tid & 31, wid = tid >> 5;
    int head = tid >> 6, f4 = tid & 63;
    __shared__ int ssrc[GCH];
    __shared__ float slog[GCH][4];
    __shared__ float wt[GCH][4];
    __shared__ float sm4[4], ss4[4], sf4[4];
    __shared__ float sred[1024];
    __shared__ float sw[8];
    __shared__ float sMu, sVar;

    int beg = g_rowptr[n];
    int deg = g_rowptr[n + 1] - beg;

    float4 adv = *(const float4*)&g_ad[n * 4];
    float4 cv = *(const float4*)&g_cvec[l * 4];
    float lw = g_loopw[l * NN + n];
    if (tid < 4) {
        float sl = lrelu(g_as[n * 4 + tid] + g_ad[n * 4 + tid] + lw * g_cvec[l * 4 + tid]);
        sm4[tid] = sl;
        ss4[tid] = 1.f;
    }
    __syncthreads();

    const uint2* xp2 = (const uint2*)g_xph;   // 4 halfs per uint2
    size_t hb = (size_t)head * 64 + f4;
    float4 acc = h4tof4(xp2[(size_t)n * 256 + hb]);   // self, weight 1 at current max

    for (int ch = 0; ch < deg; ch += GCH) {
        int cnt = min(GCH, deg - ch);
        if (tid < cnt) {
            int p = beg + ch + tid;
            int s0 = g_csrc[p];
            float w = g_ew[l * EE + g_ceid[p]];
            ssrc[tid] = s0;
            float4 as4 = *(const float4*)&g_as[s0 * 4];
            slog[tid][0] = lrelu(as4.x + adv.x + w * cv.x);
            slog[tid][1] = lrelu(as4.y + adv.y + w * cv.y);
            slog[tid][2] = lrelu(as4.z + adv.z + w * cv.z);
            slog[tid][3] = lrelu(as4.w + adv.w + w * cv.w);
        }
        __syncthreads();
        if (wid < 4) {
            int h = wid;
            float cm = -1e30f;
            for (int j = lane; j < cnt; j += 32) cm = fmaxf(cm, slog[j][h]);
            for (int o = 16; o; o >>= 1) cm = fmaxf(cm, __shfl_xor_sync(0xffffffff, cm, o));
            float mold = sm4[h];
            float mnew = fmaxf(mold, cm);
            float fac = expf(mold - mnew);
            float cs = 0.f;
            for (int j = lane; j < cnt; j += 32) {
                float p = expf(slog[j][h] - mnew);
                wt[j][h] = p;
                cs += p;
            }
            for (int o = 16; o; o >>= 1) cs += __shfl_xor_sync(0xffffffff, cs, o);
            if (lane == 0) {
                ss4[h] = ss4[h] * fac + cs;
                sm4[h] = mnew;
                sf4[h] = fac;
            }
        }
        __syncthreads();
        float f = sf4[head];
        acc.x *= f; acc.y *= f; acc.z *= f; acc.w *= f;
        int j = 0;
        for (; j + 4 <= cnt; j += 4) {
            float a0 = wt[j][head], a1 = wt[j + 1][head];
            float a2 = wt[j + 2][head], a3 = wt[j + 3][head];
            float4 v0 = h4tof4(xp2[(size_t)ssrc[j] * 256 + hb]);
            float4 v1 = h4tof4(xp2[(size_t)ssrc[j + 1] * 256 + hb]);
            float4 v2 = h4tof4(xp2[(size_t)ssrc[j + 2] * 256 + hb]);
            float4 v3 = h4tof4(xp2[(size_t)ssrc[j + 3] * 256 + hb]);
            acc.x += a0 * v0.x + a1 * v1.x + a2 * v2.x + a3 * v3.x;
            acc.y += a0 * v0.y + a1 * v1.y + a2 * v2.y + a3 * v3.y;
            acc.z += a0 * v0.z + a1 * v1.z + a2 * v2.z + a3 * v3.z;
            acc.w += a0 * v0.w + a1 * v1.w + a2 * v2.w + a3 * v3.w;
        }
        for (; j < cnt; j++) {
            float a = wt[j][head];
            float4 v = h4tof4(xp2[(size_t)ssrc[j] * 256 + hb]);
            acc.x += a * v.x;
            acc.y += a * v.y;
            acc.z += a * v.z;
            acc.w += a * v.w;
        }
        __syncthreads();   // before smem reuse next chunk
    }

    float inv = 0.25f / ss4[head];
    acc.x *= inv; acc.y *= inv; acc.z *= inv; acc.w *= inv;
    *(float4*)&sred[head * 256 + f4 * 4] = acc;
    __syncthreads();

    float h = sred[tid] + sred[256 + tid] + sred[512 + tid] + sred[768 + tid] + gat_b[tid];

    float v = h;
    for (int o = 16; o; o >>= 1) v += __shfl_xor_sync(0xffffffff, v, o);
    if (lane == 0) sw[wid] = v;
    __syncthreads();
    if (tid == 0) {
        float t = sw[0] + sw[1] + sw[2] + sw[3] + sw[4] + sw[5] + sw[6] + sw[7];
        sMu = t * (1.f / 256.f);
    }
    __syncthreads();
    float df = h - sMu;
    v = df * df;
    for (int o = 16; o; o >>= 1) v += __shfl_xor_sync(0xffffffff, v, o);
    __syncthreads();
    if (lane == 0) sw[wid] = v;
    __syncthreads();
    if (tid == 0) {
        float t = sw[0] + sw[1] + sw[2] + sw[3] + sw[4] + sw[5] + sw[6] + sw[7];
        sVar = t * (1.f / 256.f);
    }
    __syncthreads();
    float y = ln_g[tid] * df * rsqrtf(sVar + 1e-5f) + ln_b[tid];
    size_t idx = (size_t)n * 256 + tid;
    // residual from exact fp16 hi/lo reconstruction (error ~2^-22)
    float xr = __half2float(xh[idx]) + __half2float(xl[idx]);
    float o = fmaxf(xr + y, 0.f);
    if (outF) outF[idx] = o;
    __half hh = __float2half(o);
    xh[idx] = hh;
    xl[idx] = __float2half(o - __half2float(hh));
}

// ---------------- launch ----------------
extern "C" void kernel_launch(void* const* d_in, const int* in_sizes, int n_in,
                              void* d_out, int out_size) {
    const float* node_features = (const float*)d_in[0];
    const float* edge_attr     = (const float*)d_in[1];
    const float* enc_w         = (const float*)d_in[2];
    const float* enc_b         = (const float*)d_in[3];
    const float* edge_enc_w    = (const float*)d_in[4];
    const float* edge_enc_b    = (const float*)d_in[5];
    const float* gat_w         = (const float*)d_in[6];
    const float* att_src       = (const float*)d_in[7];
    const float* att_dst       = (const float*)d_in[8];
    const float* att_edge      = (const float*)d_in[9];
    const float* lin_edge_w    = (const float*)d_in[10];
    const float* gat_b         = (const float*)d_in[11];
    const float* ln_g          = (const float*)d_in[12];
    const float* ln_b          = (const float*)d_in[13];
    const float* head_w1       = (const float*)d_in[14];
    const float* head_b1       = (const float*)d_in[15];
    const float* head_w2       = (const float*)d_in[16];
    const float* head_b2       = (const float*)d_in[17];
    const int*   src           = (const int*)d_in[18];
    const int*   dst           = src + EE;
    float* out = (float*)d_out;

    __half *pxph, *pAh, *pAl, *pXh, *pXl, *pBh, *pBl, *pB2h, *pB2l;
    cudaGetSymbolAddress((void**)&pxph, g_xph);
    cudaGetSymbolAddress((void**)&pAh, g_Ah);
    cudaGetSymbolAddress((void**)&pAl, g_Al);
    cudaGetSymbolAddress((void**)&pXh, g_Xh);
    cudaGetSymbolAddress((void**)&pXl, g_Xl);
    cudaGetSymbolAddress((void**)&pBh, g_Bh);
    cudaGetSymbolAddress((void**)&pBl, g_Bl);
    cudaGetSymbolAddress((void**)&pB2h, g_B2h);
    cudaGetSymbolAddress((void**)&pB2l, g_B2l);

    cudaFuncSetAttribute(k_mma, cudaFuncAttributeMaxDynamicSharedMemorySize, GEMM_SMEM);

    const int MT = (NN + 127) / 128;  // 157 M-tiles

    // fork/join side stream + events (created per call; kernel_launch runs only a few times)
    cudaStream_t s2;
    cudaStreamCreateWithFlags(&s2, cudaStreamNonBlocking);
    cudaEvent_t eF, eEnc, w0, w1, w2e, wHe, eP, eMenc, eMx0, eMx1;
    cudaEventCreateWithFlags(&eF, cudaEventDisableTiming);
    cudaEventCreateWithFlags(&eEnc, cudaEventDisableTiming);
    cudaEventCreateWithFlags(&w0, cudaEventDisableTiming);
    cudaEventCreateWithFlags(&w1, cudaEventDisableTiming);
    cudaEventCreateWithFlags(&w2e, cudaEventDisableTiming);
    cudaEventCreateWithFlags(&wHe, cudaEventDisableTiming);
    cudaEventCreateWithFlags(&eP, cudaEventDisableTiming);
    cudaEventCreateWithFlags(&eMenc, cudaEventDisableTiming);
    cudaEventCreateWithFlags(&eMx0, cudaEventDisableTiming);
    cudaEventCreateWithFlags(&eMx1, cudaEventDisableTiming);

    // ---- fork ----
    cudaEventRecord(eF, 0);
    cudaStreamWaitEvent(s2, eF, 0);

    // ---- side stream part 1: weight converts (enc->B, gat0->B2) + all graph preprocessing ----
    k_cvtBT<<<(NDIM * HD + 255) / 256, 256, 0, s2>>>(enc_w, pBh, pBl, NDIM, HD);
    cudaEventRecord(eEnc, s2);
    k_cvtBT<<<(HD * 1024 + 255) / 256, 256, 0, s2>>>(gat_w, pB2h, pB2l, HD, 1024);
    cudaEventRecord(w0, s2);
    k_zero<<<(NN + 255) / 256, 256, 0, s2>>>();
    k_count<<<(EE + 255) / 256, 256, 0, s2>>>(dst);
    k_scan<<<1, 1024, 0, s2>>>();
    k_scatter<<<(EE + 255) / 256, 256, 0, s2>>>(src, dst);
    k_wmean<<<NL * EDIM, 256, 0, s2>>>(edge_enc_w);
    k_bmean<<<NL, 256, 0, s2>>>(edge_enc_b);
    k_cvec<<<NL * NHEADS, 256, 0, s2>>>(lin_edge_w, att_edge);
    k_ew3<<<(EE + 7) / 8, 256, 0, s2>>>(edge_attr);
    k_loopw3<<<(NN + 255) / 256, 256, 0, s2>>>();
    cudaEventRecord(eP, s2);

    // ---- main part 1: encoder + xp0 ----
    k_zeroAS<<<(NN * 4 + 255) / 256, 256>>>();
    k_cvtA<<<(NN * NDIM + 255) / 256, 256>>>(node_features, pAh, pAl, NN * NDIM);
    cudaStreamWaitEvent(0, eEnc, 0);
    k_mma<<<dim3(HD / 128, MT), 256, GEMM_SMEM>>>(pAh, pAl, pBh, pBl,
                                                  nullptr, nullptr, pXh, pXl,
                                                  NN, HD, NDIM, enc_b, 1, nullptr, nullptr,
                                                  nullptr, nullptr, nullptr);
    cudaEventRecord(eMenc, 0);
    cudaStreamWaitEvent(0, w0, 0);
    k_mma<<<dim3(1024 / 128, MT), 256, GEMM_SMEM>>>(pXh, pXl, pB2h, pB2l,
                                                    nullptr, pxph, nullptr, nullptr,
                                                    NN, 1024, HD, nullptr, 0,
                                                    att_src, att_dst,
                                                    nullptr, nullptr, nullptr);
    cudaEventRecord(eMx0, 0);

    // ---- side part 2: gat1->B (after enc GEMM frees B), gat2->B2 (after xp0 frees B2) ----
    cudaStreamWaitEvent(s2, eMenc, 0);
    k_cvtBT<<<(HD * 1024 + 255) / 256, 256, 0, s2>>>(gat_w + (size_t)256 * 1024,
                                                     pBh, pBl, HD, 1024);
    cudaEventRecord(w1, s2);
    cudaStreamWaitEvent(s2, eMx0, 0);
    k_cvtBT<<<(HD * 1024 + 255) / 256, 256, 0, s2>>>(gat_w + (size_t)2 * 256 * 1024,
                                                     pB2h, pB2l, HD, 1024);
    cudaEventRecord(w2e, s2);

    // ---- main part 2: gather0 + xp1 ----
    cudaStreamWaitEvent(0, eP, 0);
    k_gather<<<NN, 256>>>(nullptr, pXh, pXl, 0, gat_b, ln_g, ln_b);
    k_zeroAS<<<(NN * 4 + 255) / 256, 256>>>();
    cudaStreamWaitEvent(0, w1, 0);
    k_mma<<<dim3(1024 / 128, MT), 256, GEMM_SMEM>>>(pXh, pXl, pBh, pBl,
                                                    nullptr, pxph, nullptr, nullptr,
                                                    NN, 1024, HD, nullptr, 0,
                                                    att_src + 1024, att_dst + 1024,
                                                    nullptr, nullptr, nullptr);
    cudaEventRecord(eMx1, 0);

    // ---- side part 3: heads->B (after xp1 frees B) ----
    cudaStreamWaitEvent(s2, eMx1, 0);
    k_cvtHW<<<(512 * 256 + 255) / 256, 256, 0, s2>>>(head_w1, pBh, pBl);
    cudaEventRecord(wHe, s2);

    // ---- main part 3: gather1 + xp2 + gather2 + fused heads ----
    k_gather<<<NN, 256>>>(nullptr, pXh, pXl, 1, gat_b + 256, ln_g + 256, ln_b + 256);
    k_zeroAS<<<(NN * 4 + 255) / 256, 256>>>();
    cudaStreamWaitEvent(0, w2e, 0);
    k_mma<<<dim3(1024 / 128, MT), 256, GEMM_SMEM>>>(pXh, pXl, pB2h, pB2l,
                                                    nullptr, pxph, nullptr, nullptr,
                                                    NN, 1024, HD, nullptr, 0,
                                                    att_src + 2048, att_dst + 2048,
                                                    nullptr, nullptr, nullptr);
    k_gather<<<NN, 256>>>(out + 4 * NN, pXh, pXl, 2, gat_b + 512, ln_g + 512, ln_b + 512);
    cudaStreamWaitEvent(0, wHe, 0);
    k_mma<<<dim3(512 / 128, MT), 256, GEMM_SMEM>>>(pXh, pXl, pBh, pBl,
                                                   nullptr, nullptr, nullptr, nullptr,
                                                   NN, 512, HD, head_b1, 0, nullptr, nullptr,
                                                   head_w2, head_b2, out);
}